// round 1
// baseline (speedup 1.0000x reference)
#include <cuda_runtime.h>
#include <cuda_bf16.h>
#include <math.h>

// ---------------------------------------------------------------------------
// MoE FFN (top-2 of 8 experts), H=1024, I=4096, T up to 8192 tokens.
// Pipeline: zero counts -> gate (fp64 logits, top2, softmax, build per-expert
// slot lists) -> GEMM1 (x @ W1^T + b1, GELU) -> GEMM2 (h @ W2^T + b2, *w)
// -> combine (out[t] = y[2t] + y[2t+1]).
// All scratch in __device__ globals (no allocations). No float atomics.
// ---------------------------------------------------------------------------

#define HID   1024
#define INTER 4096
#define NEXP  8
#define TMAX  8192
#define NSLOT (2 * TMAX)

__device__ float d_h[(size_t)NSLOT * INTER];   // 268 MB fp32 intermediate
__device__ float d_y[(size_t)NSLOT * HID];     // 67 MB per-slot outputs
__device__ float d_slot_w[NSLOT];              // combine weight per slot
__device__ int   d_slot_list[NEXP * TMAX];     // slot ids per expert
__device__ int   d_counts[NEXP];

// ---------------- f32x2 helpers (Blackwell packed fp32 FMA) ----------------

__device__ __forceinline__ unsigned long long ffma2(unsigned long long a,
                                                    unsigned long long b,
                                                    unsigned long long c) {
    unsigned long long d;
    asm("fma.rn.f32x2 %0, %1, %2, %3;" : "=l"(d) : "l"(a), "l"(b), "l"(c));
    return d;
}

__device__ __forceinline__ unsigned long long dup2(float x) {
    unsigned long long r;
    asm("mov.b64 %0, {%1, %1};" : "=l"(r) : "f"(x));
    return r;
}

__device__ __forceinline__ float2 unpack2(unsigned long long v) {
    float2 r;
    asm("mov.b64 {%0, %1}, %2;" : "=f"(r.x), "=f"(r.y) : "l"(v));
    return r;
}

// ------------------------------- kernels -----------------------------------

__global__ void zero_counts_kernel() {
    if (threadIdx.x < NEXP) d_counts[threadIdx.x] = 0;
}

// One warp per token. Logits accumulated in fp64 to make routing robust
// against fp32 summation-order noise vs the reference.
__global__ void gate_kernel(const float* __restrict__ x,
                            const float* __restrict__ gw, int T) {
    int warp = (blockIdx.x * blockDim.x + threadIdx.x) >> 5;
    int lane = threadIdx.x & 31;
    if (warp >= T) return;
    const float* xr = x + (size_t)warp * HID;

    double acc[NEXP];
#pragma unroll
    for (int e = 0; e < NEXP; e++) acc[e] = 0.0;

    for (int i = lane; i < HID; i += 32) {
        float xv = xr[i];
#pragma unroll
        for (int e = 0; e < NEXP; e++)
            acc[e] += (double)xv * (double)gw[e * HID + i];
    }
#pragma unroll
    for (int e = 0; e < NEXP; e++) {
#pragma unroll
        for (int o = 16; o > 0; o >>= 1)
            acc[e] += __shfl_down_sync(0xffffffffu, acc[e], o);
    }

    if (lane == 0) {
        float v[NEXP];
#pragma unroll
        for (int e = 0; e < NEXP; e++) v[e] = (float)acc[e];
        // top-2, lowest index wins ties (matches jax.lax.top_k)
        float bv = -1e30f, sv = -1e30f;
        int bi = 0, si = 0;
#pragma unroll
        for (int e = 0; e < NEXP; e++) {
            float val = v[e];
            if (val > bv) { sv = bv; si = bi; bv = val; bi = e; }
            else if (val > sv) { sv = val; si = e; }
        }
        float e1 = expf(sv - bv);
        float s  = 1.0f + e1;
        d_slot_w[2 * warp + 0] = 1.0f / s;
        d_slot_w[2 * warp + 1] = e1 / s;
        int p0 = atomicAdd(&d_counts[bi], 1);
        d_slot_list[bi * TMAX + p0] = 2 * warp;
        int p1 = atomicAdd(&d_counts[si], 1);
        d_slot_list[si * TMAX + p1] = 2 * warp + 1;
    }
}

// Tiled gather-GEMM. 64x64 tile, BK=16, 256 threads, 4x4 outputs/thread,
// inner loop in packed f32x2 FMA (rows paired).
#define BM 64
#define BN 64
#define BK 16

template <int KDIM, int NDIM, bool FFN1>
__global__ void __launch_bounds__(256)
moe_gemm(const float* __restrict__ X,   // token activations (used by FFN1)
         const float* __restrict__ W,   // [NEXP][NDIM][KDIM]
         const float* __restrict__ Bv)  // [NEXP][NDIM]
{
    const int e   = blockIdx.z;
    const int cnt = d_counts[e];
    const int r0  = blockIdx.y * BM;
    if (r0 >= cnt) return;
    const int n0  = blockIdx.x * BN;
    const int tid = threadIdx.x;

    __shared__ float As[BK][BM];
    __shared__ float Bs[BK][BN];
    __shared__ int   Srow[BM];

    if (tid < BM) {
        int idx = r0 + tid;
        Srow[tid] = (idx < cnt) ? d_slot_list[e * TMAX + idx] : -1;
    }
    __syncthreads();

    // loader mapping: each thread loads one float4 along K
    const int lm = tid >> 2;            // 0..63 : row (A) / n (B)
    const int lk = (tid & 3) * 4;       // 0,4,8,12

    const int aslot = Srow[lm];
    const float* Arow = nullptr;
    if (aslot >= 0)
        Arow = FFN1 ? (X + (size_t)(aslot >> 1) * KDIM)
                    : (d_h + (size_t)aslot * KDIM);
    const float* Wrow = W + ((size_t)e * NDIM + n0 + lm) * KDIM;

    unsigned long long accA[4] = {0ull, 0ull, 0ull, 0ull}; // rows tm,tm+1
    unsigned long long accB[4] = {0ull, 0ull, 0ull, 0ull}; // rows tm+2,tm+3
    const int tm = (tid >> 4) * 4;      // 0..60
    const int tn = (tid & 15) * 4;      // 0..60

    for (int k0 = 0; k0 < KDIM; k0 += BK) {
        float4 av = Arow ? *(const float4*)(Arow + k0 + lk)
                         : make_float4(0.f, 0.f, 0.f, 0.f);
        float4 wv = *(const float4*)(Wrow + k0 + lk);
        __syncthreads();   // previous tile's compute done
        As[lk + 0][lm] = av.x; As[lk + 1][lm] = av.y;
        As[lk + 2][lm] = av.z; As[lk + 3][lm] = av.w;
        Bs[lk + 0][lm] = wv.x; Bs[lk + 1][lm] = wv.y;
        Bs[lk + 2][lm] = wv.z; Bs[lk + 3][lm] = wv.w;
        __syncthreads();

#pragma unroll
        for (int kk = 0; kk < BK; kk++) {
            unsigned long long a01 =
                *(const unsigned long long*)&As[kk][tm];
            unsigned long long a23 =
                *(const unsigned long long*)&As[kk][tm + 2];
            float4 b4 = *(const float4*)&Bs[kk][tn];
            unsigned long long bd;
            bd = dup2(b4.x); accA[0] = ffma2(a01, bd, accA[0]);
                             accB[0] = ffma2(a23, bd, accB[0]);
            bd = dup2(b4.y); accA[1] = ffma2(a01, bd, accA[1]);
                             accB[1] = ffma2(a23, bd, accB[1]);
            bd = dup2(b4.z); accA[2] = ffma2(a01, bd, accA[2]);
                             accB[2] = ffma2(a23, bd, accB[2]);
            bd = dup2(b4.w); accA[3] = ffma2(a01, bd, accA[3]);
                             accB[3] = ffma2(a23, bd, accB[3]);
        }
    }

    // unpack: vals[im][j], im = row-within-quad, j = col
    float vals[4][4];
#pragma unroll
    for (int j = 0; j < 4; j++) {
        float2 rA = unpack2(accA[j]);
        float2 rB = unpack2(accB[j]);
        vals[0][j] = rA.x; vals[1][j] = rA.y;
        vals[2][j] = rB.x; vals[3][j] = rB.y;
    }

    const float* brow = Bv + (size_t)e * NDIM + n0 + tn;
    float b0 = brow[0], b1v = brow[1], b2v = brow[2], b3v = brow[3];

#pragma unroll
    for (int im = 0; im < 4; im++) {
        int m = tm + im;
        int slotm = Srow[m];
        if (slotm < 0) continue;
        float4 o;
        o.x = vals[im][0] + b0;
        o.y = vals[im][1] + b1v;
        o.z = vals[im][2] + b2v;
        o.w = vals[im][3] + b3v;
        if (FFN1) {
            // exact GELU: 0.5*x*(1+erf(x/sqrt(2)))
            o.x = 0.5f * o.x * (1.0f + erff(o.x * 0.7071067811865475f));
            o.y = 0.5f * o.y * (1.0f + erff(o.y * 0.7071067811865475f));
            o.z = 0.5f * o.z * (1.0f + erff(o.z * 0.7071067811865475f));
            o.w = 0.5f * o.w * (1.0f + erff(o.w * 0.7071067811865475f));
            *(float4*)(d_h + (size_t)slotm * NDIM + n0 + tn) = o;
        } else {
            float wm = d_slot_w[slotm];
            o.x *= wm; o.y *= wm; o.z *= wm; o.w *= wm;
            *(float4*)(d_y + (size_t)slotm * NDIM + n0 + tn) = o;
        }
    }
}

__global__ void combine_kernel(float* __restrict__ out, int T) {
    int i = blockIdx.x * blockDim.x + threadIdx.x;   // float4 index
    int total = T * (HID / 4);
    if (i >= total) return;
    int h4 = i & (HID / 4 - 1);
    int t  = i >> 8;                                  // HID/4 = 256
    const float4* y4 = (const float4*)d_y;
    float4 a = y4[(size_t)(2 * t) * (HID / 4) + h4];
    float4 b = y4[(size_t)(2 * t + 1) * (HID / 4) + h4];
    float4 r;
    r.x = a.x + b.x; r.y = a.y + b.y; r.z = a.z + b.z; r.w = a.w + b.w;
    ((float4*)out)[i] = r;
}

// ------------------------------- launch ------------------------------------

extern "C" void kernel_launch(void* const* d_in, const int* in_sizes, int n_in,
                              void* d_out, int out_size) {
    const float* x   = (const float*)d_in[0];   // [T, 1024]
    const float* gw  = (const float*)d_in[1];   // [8, 1024]
    const float* W1  = (const float*)d_in[2];   // [8, 4096, 1024]
    const float* b1  = (const float*)d_in[3];   // [8, 4096]
    const float* W2  = (const float*)d_in[4];   // [8, 1024, 4096]
    const float* b2  = (const float*)d_in[5];   // [8, 1024]
    float* out = (float*)d_out;

    int T = in_sizes[0] / HID;                  // 8192

    zero_counts_kernel<<<1, 32>>>();
    gate_kernel<<<(T + 7) / 8, 256>>>(x, gw, T);

    dim3 g1(INTER / BN, (T + BM - 1) / BM, NEXP);
    moe_gemm<HID, INTER, true><<<g1, 256>>>(x, W1, b1);

    dim3 g2(HID / BN, (T + BM - 1) / BM, NEXP);
    moe_gemm<INTER, HID, false><<<g2, 256>>>(x, W2, b2);

    combine_kernel<<<(T * (HID / 4) + 255) / 256, 256>>>(out, T);
}

// round 4
// speedup vs baseline: 3.4559x; 3.4559x over previous
#include <cuda_runtime.h>
#include <cuda_bf16.h>
#include <math.h>
#include <stdint.h>

// ---------------------------------------------------------------------------
// MoE FFN top-2/8, H=1024, I=4096, T<=8192, fp32 in/out.
// R3: legacy tensor-core path (mma.sync bf16, split-precision hi+lo planes).
//   zero -> gate(fp64 logits, top2, slot lists)
//   split x,W1,W2 into bf16 hi/lo plane pairs (one-time per launch)
//   GEMM1: x @ W1^T + b1, GELU -> h (stored as hi/lo bf16 planes)
//   GEMM2: h @ W2^T + b2, *slot_w -> d_y fp32
//   combine: out[t] = y[2t] + y[2t+1]
// No tcgen05 (harness compiles for plain sm_100: tcgen05 unavailable).
// ---------------------------------------------------------------------------

#define HID   1024
#define INTER 4096
#define NEXP  8
#define TMAX  8192
#define NSLOT (2 * TMAX)

#define WCNT ((size_t)NEXP * (size_t)INTER * (size_t)HID)  // 33.55M elems
#define XOFF ((size_t)TMAX * (size_t)HID)
#define HOFF ((size_t)NSLOT * (size_t)INTER)

__device__ __nv_bfloat16 d_xs[2 * XOFF];    // x hi plane, then lo plane
__device__ __nv_bfloat16 d_w1s[2 * WCNT];   // W1 hi, lo
__device__ __nv_bfloat16 d_w2s[2 * WCNT];   // W2 hi, lo
__device__ __nv_bfloat16 d_hs[2 * HOFF];    // h  hi, lo
__device__ float d_y[(size_t)NSLOT * (size_t)HID];
__device__ float d_slot_w[NSLOT];
__device__ int   d_slot_list[NEXP * TMAX];
__device__ int   d_counts[NEXP];

// ------------------------------ PTX helpers --------------------------------

__device__ __forceinline__ uint32_t smem_u32(const void* p) {
    uint32_t a;
    asm("{ .reg .u64 t; cvta.to.shared.u64 t, %1; cvt.u32.u64 %0, t; }"
        : "=r"(a) : "l"(p));
    return a;
}

__device__ __forceinline__ void cp16(uint32_t saddr, const void* g) {
    asm volatile("cp.async.cg.shared.global [%0], [%1], 16;"
                 :: "r"(saddr), "l"(g));
}
#define CP_COMMIT() asm volatile("cp.async.commit_group;" ::: "memory")
#define CP_WAIT(N)  asm volatile("cp.async.wait_group %0;" :: "n"(N) : "memory")

__device__ __forceinline__ void ldm_x4(uint32_t* r, uint32_t addr) {
    asm volatile("ldmatrix.sync.aligned.m8n8.x4.shared.b16 {%0,%1,%2,%3}, [%4];"
                 : "=r"(r[0]), "=r"(r[1]), "=r"(r[2]), "=r"(r[3]) : "r"(addr));
}

__device__ __forceinline__ void mma16816(float* c, const uint32_t* a,
                                         uint32_t b0, uint32_t b1) {
    asm volatile(
        "mma.sync.aligned.m16n8k16.row.col.f32.bf16.bf16.f32 "
        "{%0,%1,%2,%3}, {%4,%5,%6,%7}, {%8,%9}, {%0,%1,%2,%3};"
        : "+f"(c[0]), "+f"(c[1]), "+f"(c[2]), "+f"(c[3])
        : "r"(a[0]), "r"(a[1]), "r"(a[2]), "r"(a[3]), "r"(b0), "r"(b1));
}

// ------------------------------ gating -------------------------------------

__global__ void zero_counts_kernel() {
    if (threadIdx.x < NEXP) d_counts[threadIdx.x] = 0;
}

__global__ void gate_kernel(const float* __restrict__ x,
                            const float* __restrict__ gw, int T) {
    int warp = (blockIdx.x * blockDim.x + threadIdx.x) >> 5;
    int lane = threadIdx.x & 31;
    if (warp >= T) return;
    const float* xr = x + (size_t)warp * HID;

    double acc[NEXP];
#pragma unroll
    for (int e = 0; e < NEXP; e++) acc[e] = 0.0;
    for (int i = lane; i < HID; i += 32) {
        float xv = xr[i];
#pragma unroll
        for (int e = 0; e < NEXP; e++)
            acc[e] += (double)xv * (double)gw[e * HID + i];
    }
#pragma unroll
    for (int e = 0; e < NEXP; e++) {
#pragma unroll
        for (int o = 16; o > 0; o >>= 1)
            acc[e] += __shfl_down_sync(0xffffffffu, acc[e], o);
    }
    if (lane == 0) {
        float v[NEXP];
#pragma unroll
        for (int e = 0; e < NEXP; e++) v[e] = (float)acc[e];
        float bv = -1e30f, sv = -1e30f;
        int bi = 0, si = 0;
#pragma unroll
        for (int e = 0; e < NEXP; e++) {
            float val = v[e];
            if (val > bv) { sv = bv; si = bi; bv = val; bi = e; }
            else if (val > sv) { sv = val; si = e; }
        }
        float e1 = expf(sv - bv);
        float s = 1.0f + e1;
        d_slot_w[2 * warp + 0] = 1.0f / s;
        d_slot_w[2 * warp + 1] = e1 / s;
        int p0 = atomicAdd(&d_counts[bi], 1);
        d_slot_list[bi * TMAX + p0] = 2 * warp;
        int p1 = atomicAdd(&d_counts[si], 1);
        d_slot_list[si * TMAX + p1] = 2 * warp + 1;
    }
}

// ----------------------- fp32 -> bf16 hi/lo split --------------------------

__global__ void split_kernel(const float* __restrict__ src,
                             __nv_bfloat16* __restrict__ dst,
                             size_t n4, size_t off) {
    size_t i = (size_t)blockIdx.x * blockDim.x + threadIdx.x;
    if (i >= n4) return;
    float4 v = ((const float4*)src)[i];
    __nv_bfloat16 h0 = __float2bfloat16_rn(v.x);
    __nv_bfloat16 h1 = __float2bfloat16_rn(v.y);
    __nv_bfloat16 h2 = __float2bfloat16_rn(v.z);
    __nv_bfloat16 h3 = __float2bfloat16_rn(v.w);
    __nv_bfloat16 l0 = __float2bfloat16_rn(v.x - __bfloat162float(h0));
    __nv_bfloat16 l1 = __float2bfloat16_rn(v.y - __bfloat162float(h1));
    __nv_bfloat16 l2 = __float2bfloat16_rn(v.z - __bfloat162float(h2));
    __nv_bfloat16 l3 = __float2bfloat16_rn(v.w - __bfloat162float(h3));
    ushort4 hv = make_ushort4(__bfloat16_as_ushort(h0), __bfloat16_as_ushort(h1),
                              __bfloat16_as_ushort(h2), __bfloat16_as_ushort(h3));
    ushort4 lv = make_ushort4(__bfloat16_as_ushort(l0), __bfloat16_as_ushort(l1),
                              __bfloat16_as_ushort(l2), __bfloat16_as_ushort(l3));
    *(ushort4*)(dst + 4 * i)       = hv;
    *(ushort4*)(dst + off + 4 * i) = lv;
}

// --------------------------- split-bf16 HMMA GEMM --------------------------
// CTA tile 128(M) x 256(N), BK=32 bf16. 8 warps of 64x64.
// smem per buffer: A hi/lo (128x32x2B each = 8KB) + B hi/lo (256x32x2B = 16KB)
// rows are 64B; swizzled chunk' = chunk ^ ((row>>1)&3) -> conflict-free ldmatrix.

#define BM 128
#define BN 256
#define BK 32

#define ABUF_HI 0
#define ABUF_LO 8192
#define BBUF_HI 16384
#define BBUF_LO 32768
#define BUFSZ   49152
#define SM_BUF  1024                         // Srow in [0,512)
#define SMEM_TOTAL (SM_BUF + 2 * BUFSZ)      // 99328 B

template <int KDIM, int NDIM, bool FFN1>
__global__ void __launch_bounds__(256, 1)
moe_gemm_mma(const float* __restrict__ Bv)   // bias [NEXP][NDIM]
{
    const int e   = blockIdx.z;
    const int cnt = d_counts[e];
    const int r0  = blockIdx.y * BM;
    if (r0 >= cnt) return;
    const int n0  = blockIdx.x * BN;

    const __nv_bfloat16* __restrict__ Abase = FFN1 ? d_xs : d_hs;
    const __nv_bfloat16* __restrict__ Wbase = FFN1 ? d_w1s : d_w2s;
    const size_t AOFF = FFN1 ? XOFF : HOFF;

    extern __shared__ __align__(128) char smem[];
    const uint32_t sb = smem_u32(smem);
    const int tid = threadIdx.x;

    int* Srow = (int*)smem;
    if (tid < BM) {
        int idx = r0 + tid;
        Srow[tid] = (idx < cnt) ? d_slot_list[e * TMAX + idx] : -1;
    }
    __syncthreads();

    // ---- loader precompute: thread -> (row lr, 16B chunk lch) -------------
    const int lr  = tid >> 2;        // 0..63
    const int lch = tid & 3;         // 0..3
    const uint32_t swA0 = (uint32_t)lr * 64u +
                          (uint32_t)((lch ^ ((lr >> 1) & 3)) << 4);
    const uint32_t swA1 = swA0 + 4096u;      // row lr+64 (same xor phase)

    int s0 = Srow[lr], s1 = Srow[lr + 64];
    const __nv_bfloat16* aptr0 =
        Abase + (size_t)(s0 < 0 ? 0 : (FFN1 ? (s0 >> 1) : s0)) * KDIM + lch * 8;
    const __nv_bfloat16* aptr1 =
        Abase + (size_t)(s1 < 0 ? 0 : (FFN1 ? (s1 >> 1) : s1)) * KDIM + lch * 8;
    const __nv_bfloat16* bptr =
        Wbase + ((size_t)e * NDIM + n0 + lr) * KDIM + lch * 8;

    auto load_chunk = [&](int c, uint32_t dbuf) {
        const int koff = c * BK;
        cp16(dbuf + ABUF_HI + swA0, aptr0 + koff);
        cp16(dbuf + ABUF_LO + swA0, aptr0 + AOFF + koff);
        cp16(dbuf + ABUF_HI + swA1, aptr1 + koff);
        cp16(dbuf + ABUF_LO + swA1, aptr1 + AOFF + koff);
#pragma unroll
        for (int i = 0; i < 4; i++) {
            const __nv_bfloat16* br = bptr + (size_t)i * 64 * KDIM + koff;
            cp16(dbuf + BBUF_HI + swA0 + i * 4096u, br);
            cp16(dbuf + BBUF_LO + swA0 + i * 4096u, br + WCNT);
        }
    };

    // ---- compute precompute ----------------------------------------------
    const int wid = tid >> 5, l = tid & 31;
    const int wm = wid >> 2;          // 0..1  (M half)
    const int wn = wid & 3;           // 0..3  (N quarter)
    const int g  = l >> 2, tg = l & 3;

    const int arow_l = wm * 64 + (l & 15);
    const uint32_t a_rowoff = (uint32_t)arow_l * 64u;
    const int axr = (arow_l >> 1) & 3;
    const int a_chsel = l >> 4;       // +0/+1 chunk

    const int brow_l = wn * 64 + ((l >> 4) << 3) + (l & 7);
    const uint32_t b_rowoff = (uint32_t)brow_l * 64u;
    const int bxr = (brow_l >> 1) & 3;
    const int b_chsel = (l >> 3) & 1;

    float acc[4][8][4];
#pragma unroll
    for (int a = 0; a < 4; a++)
#pragma unroll
        for (int b = 0; b < 8; b++)
#pragma unroll
            for (int q = 0; q < 4; q++) acc[a][b][q] = 0.0f;

    constexpr int NC = KDIM / BK;

    load_chunk(0, sb + SM_BUF);
    CP_COMMIT();

    for (int c = 0; c < NC; c++) {
        const uint32_t sbuf = sb + SM_BUF + (uint32_t)(c & 1) * BUFSZ;
        if (c + 1 < NC) {
            load_chunk(c + 1, sb + SM_BUF + (uint32_t)((c + 1) & 1) * BUFSZ);
            CP_COMMIT();
            CP_WAIT(1);
        } else {
            CP_WAIT(0);
        }
        __syncthreads();

#pragma unroll
        for (int ks = 0; ks < 2; ks++) {
            uint32_t ah[4][4], al[4][4];
            const uint32_t aoff =
                (uint32_t)(((2 * ks + a_chsel) ^ axr) << 4);
#pragma unroll
            for (int mi = 0; mi < 4; mi++) {
                uint32_t addr = sbuf + ABUF_HI + a_rowoff +
                                (uint32_t)mi * 1024u + aoff;
                ldm_x4(ah[mi], addr);
                ldm_x4(al[mi], addr + 8192u);
            }
            const uint32_t boff =
                (uint32_t)(((2 * ks + b_chsel) ^ bxr) << 4);
#pragma unroll
            for (int jp = 0; jp < 4; jp++) {
                uint32_t baddr = sbuf + BBUF_HI + b_rowoff +
                                 (uint32_t)jp * 1024u + boff;
                uint32_t bh[4], bl[4];
                ldm_x4(bh, baddr);
                ldm_x4(bl, baddr + 16384u);
#pragma unroll
                for (int mi = 0; mi < 4; mi++) {
                    mma16816(acc[mi][2 * jp],     ah[mi], bh[0], bh[1]);
                    mma16816(acc[mi][2 * jp],     ah[mi], bl[0], bl[1]);
                    mma16816(acc[mi][2 * jp],     al[mi], bh[0], bh[1]);
                    mma16816(acc[mi][2 * jp + 1], ah[mi], bh[2], bh[3]);
                    mma16816(acc[mi][2 * jp + 1], ah[mi], bl[2], bl[3]);
                    mma16816(acc[mi][2 * jp + 1], al[mi], bh[2], bh[3]);
                }
            }
        }
        __syncthreads();
    }

    // ---- epilogue ---------------------------------------------------------
    const float* bias = Bv + (size_t)e * NDIM;
#pragma unroll
    for (int mi = 0; mi < 4; mi++) {
        const int lr0 = wm * 64 + mi * 16 + g;
        const int slotA = Srow[lr0];
        const int slotB = Srow[lr0 + 8];
#pragma unroll
        for (int nj = 0; nj < 8; nj++) {
            const int col = n0 + wn * 64 + nj * 8 + 2 * tg;
            const float b0 = bias[col], b1 = bias[col + 1];
            if (FFN1) {
                if (slotA >= 0) {
                    float v0 = acc[mi][nj][0] + b0;
                    float v1 = acc[mi][nj][1] + b1;
                    v0 = 0.5f * v0 * (1.0f + erff(v0 * 0.7071067811865475f));
                    v1 = 0.5f * v1 * (1.0f + erff(v1 * 0.7071067811865475f));
                    __nv_bfloat16 h0 = __float2bfloat16_rn(v0);
                    __nv_bfloat16 h1 = __float2bfloat16_rn(v1);
                    __nv_bfloat16 q0 = __float2bfloat16_rn(v0 - __bfloat162float(h0));
                    __nv_bfloat16 q1 = __float2bfloat16_rn(v1 - __bfloat162float(h1));
                    size_t p = (size_t)slotA * INTER + col;
                    *(__nv_bfloat162*)(d_hs + p) = __nv_bfloat162(h0, h1);
                    *(__nv_bfloat162*)(d_hs + HOFF + p) = __nv_bfloat162(q0, q1);
                }
                if (slotB >= 0) {
                    float v0 = acc[mi][nj][2] + b0;
                    float v1 = acc[mi][nj][3] + b1;
                    v0 = 0.5f * v0 * (1.0f + erff(v0 * 0.7071067811865475f));
                    v1 = 0.5f * v1 * (1.0f + erff(v1 * 0.7071067811865475f));
                    __nv_bfloat16 h0 = __float2bfloat16_rn(v0);
                    __nv_bfloat16 h1 = __float2bfloat16_rn(v1);
                    __nv_bfloat16 q0 = __float2bfloat16_rn(v0 - __bfloat162float(h0));
                    __nv_bfloat16 q1 = __float2bfloat16_rn(v1 - __bfloat162float(h1));
                    size_t p = (size_t)slotB * INTER + col;
                    *(__nv_bfloat162*)(d_hs + p) = __nv_bfloat162(h0, h1);
                    *(__nv_bfloat162*)(d_hs + HOFF + p) = __nv_bfloat162(q0, q1);
                }
            } else {
                if (slotA >= 0) {
                    float wmul = d_slot_w[slotA];
                    float2 o;
                    o.x = (acc[mi][nj][0] + b0) * wmul;
                    o.y = (acc[mi][nj][1] + b1) * wmul;
                    *(float2*)(d_y + (size_t)slotA * HID + col) = o;
                }
                if (slotB >= 0) {
                    float wmul = d_slot_w[slotB];
                    float2 o;
                    o.x = (acc[mi][nj][2] + b0) * wmul;
                    o.y = (acc[mi][nj][3] + b1) * wmul;
                    *(float2*)(d_y + (size_t)slotB * HID + col) = o;
                }
            }
        }
    }
}

// ------------------------------ combine ------------------------------------

__global__ void combine_kernel(float* __restrict__ out, int T) {
    int i = blockIdx.x * blockDim.x + threadIdx.x;
    int total = T * (HID / 4);
    if (i >= total) return;
    int h4 = i & (HID / 4 - 1);
    int t  = i >> 8;
    const float4* y4 = (const float4*)d_y;
    float4 a = y4[(size_t)(2 * t) * (HID / 4) + h4];
    float4 b = y4[(size_t)(2 * t + 1) * (HID / 4) + h4];
    float4 r;
    r.x = a.x + b.x; r.y = a.y + b.y; r.z = a.z + b.z; r.w = a.w + b.w;
    ((float4*)out)[i] = r;
}

// ------------------------------- launch ------------------------------------

extern "C" void kernel_launch(void* const* d_in, const int* in_sizes, int n_in,
                              void* d_out, int out_size) {
    const float* x  = (const float*)d_in[0];
    const float* gw = (const float*)d_in[1];
    const float* W1 = (const float*)d_in[2];
    const float* b1 = (const float*)d_in[3];
    const float* W2 = (const float*)d_in[4];
    const float* b2 = (const float*)d_in[5];
    float* out = (float*)d_out;

    int T = in_sizes[0] / HID;

    cudaFuncSetAttribute(moe_gemm_mma<HID, INTER, true>,
                         cudaFuncAttributeMaxDynamicSharedMemorySize,
                         SMEM_TOTAL);
    cudaFuncSetAttribute(moe_gemm_mma<INTER, HID, false>,
                         cudaFuncAttributeMaxDynamicSharedMemorySize,
                         SMEM_TOTAL);

    zero_counts_kernel<<<1, 32>>>();
    gate_kernel<<<(T + 7) / 8, 256>>>(x, gw, T);

    // split fp32 sources into bf16 hi/lo planes
    {
        __nv_bfloat16* dxs;  cudaGetSymbolAddress((void**)&dxs,  d_xs);
        __nv_bfloat16* dw1;  cudaGetSymbolAddress((void**)&dw1,  d_w1s);
        __nv_bfloat16* dw2;  cudaGetSymbolAddress((void**)&dw2,  d_w2s);
        size_t nx = (size_t)T * HID / 4;
        split_kernel<<<(unsigned)((nx + 255) / 256), 256>>>(x, dxs, nx, XOFF);
        size_t nw = WCNT / 4;
        split_kernel<<<(unsigned)((nw + 255) / 256), 256>>>(W1, dw1, nw, WCNT);
        split_kernel<<<(unsigned)((nw + 255) / 256), 256>>>(W2, dw2, nw, WCNT);
    }

    int mtiles = (T + BM - 1) / BM;
    dim3 g1(INTER / BN, mtiles, NEXP);
    moe_gemm_mma<HID, INTER, true><<<g1, 256, SMEM_TOTAL>>>(b1);

    dim3 g2(HID / BN, mtiles, NEXP);
    moe_gemm_mma<INTER, HID, false><<<g2, 256, SMEM_TOTAL>>>(b2);

    combine_kernel<<<(T * (HID / 4) + 255) / 256, 256>>>(out, T);
}

// round 5
// speedup vs baseline: 4.3050x; 1.2457x over previous
#include <cuda_runtime.h>
#include <cuda_bf16.h>
#include <cuda_fp16.h>
#include <math.h>
#include <stdint.h>

// ---------------------------------------------------------------------------
// MoE FFN top-2/8, H=1024, I=4096, T<=8192, fp32 in/out.
// R5: fp16-plane HMMA path.
//   x -> fp16 hi+lo planes; W1,W2 -> fp16 single plane; h -> fp16 single.
//   GEMM1: (x_hi + x_lo) @ W1^T  (2 MMA passes) + b1, GELU -> h fp16
//   GEMM2: h @ W2^T (1 MMA pass) + b2, *slot_w -> d_y fp32
//   combine: out[t] = y[2t] + y[2t+1]
// Launch order: split_x(+zero), split_w1, split_w2, gate, gemm1, gemm2,
// combine  (gemm2 = launch index 5 for ncu -s 5).
// ---------------------------------------------------------------------------

#define HID   1024
#define INTER 4096
#define NEXP  8
#define TMAX  8192
#define NSLOT (2 * TMAX)

#define WCNT ((size_t)NEXP * (size_t)INTER * (size_t)HID)
#define XOFF ((size_t)TMAX * (size_t)HID)
#define HOFF ((size_t)NSLOT * (size_t)INTER)

__device__ __half d_xs[2 * XOFF];     // x hi plane, lo plane
__device__ __half d_w1h[WCNT];        // W1 fp16
__device__ __half d_w2h[WCNT];        // W2 fp16
__device__ __half d_hs[HOFF];         // h fp16
__device__ float  d_y[(size_t)NSLOT * (size_t)HID];
__device__ float  d_slot_w[NSLOT];
__device__ int    d_slot_list[NEXP * TMAX];
__device__ int    d_counts[NEXP];

// ------------------------------ PTX helpers --------------------------------

__device__ __forceinline__ uint32_t smem_u32(const void* p) {
    uint32_t a;
    asm("{ .reg .u64 t; cvta.to.shared.u64 t, %1; cvt.u32.u64 %0, t; }"
        : "=r"(a) : "l"(p));
    return a;
}

__device__ __forceinline__ void cp16(uint32_t saddr, const void* g) {
    asm volatile("cp.async.cg.shared.global [%0], [%1], 16;"
                 :: "r"(saddr), "l"(g));
}
#define CP_COMMIT() asm volatile("cp.async.commit_group;" ::: "memory")
#define CP_WAIT(N)  asm volatile("cp.async.wait_group %0;" :: "n"(N) : "memory")

__device__ __forceinline__ void ldm_x4(uint32_t* r, uint32_t addr) {
    asm volatile("ldmatrix.sync.aligned.m8n8.x4.shared.b16 {%0,%1,%2,%3}, [%4];"
                 : "=r"(r[0]), "=r"(r[1]), "=r"(r[2]), "=r"(r[3]) : "r"(addr));
}

__device__ __forceinline__ void mma16816(float* c, const uint32_t* a,
                                         uint32_t b0, uint32_t b1) {
    asm volatile(
        "mma.sync.aligned.m16n8k16.row.col.f32.f16.f16.f32 "
        "{%0,%1,%2,%3}, {%4,%5,%6,%7}, {%8,%9}, {%0,%1,%2,%3};"
        : "+f"(c[0]), "+f"(c[1]), "+f"(c[2]), "+f"(c[3])
        : "r"(a[0]), "r"(a[1]), "r"(a[2]), "r"(a[3]), "r"(b0), "r"(b1));
}

// ---------------------------- split kernels --------------------------------

// x fp32 -> fp16 hi+lo planes; block 0 also zeroes expert counts.
__global__ void split_x_kernel(const float* __restrict__ src, size_t n4) {
    if (blockIdx.x == 0 && threadIdx.x < NEXP) d_counts[threadIdx.x] = 0;
    size_t i = (size_t)blockIdx.x * blockDim.x + threadIdx.x;
    if (i >= n4) return;
    float4 v = ((const float4*)src)[i];
    __half h0 = __float2half_rn(v.x), h1 = __float2half_rn(v.y);
    __half h2 = __float2half_rn(v.z), h3 = __float2half_rn(v.w);
    __half l0 = __float2half_rn(v.x - __half2float(h0));
    __half l1 = __float2half_rn(v.y - __half2float(h1));
    __half l2 = __float2half_rn(v.z - __half2float(h2));
    __half l3 = __float2half_rn(v.w - __half2float(h3));
    ushort4 hv = make_ushort4(__half_as_ushort(h0), __half_as_ushort(h1),
                              __half_as_ushort(h2), __half_as_ushort(h3));
    ushort4 lv = make_ushort4(__half_as_ushort(l0), __half_as_ushort(l1),
                              __half_as_ushort(l2), __half_as_ushort(l3));
    *(ushort4*)(d_xs + 4 * i)        = hv;
    *(ushort4*)(d_xs + XOFF + 4 * i) = lv;
}

// W fp32 -> fp16 single plane.
__global__ void split_w_kernel(const float* __restrict__ src,
                               __half* __restrict__ dst, size_t n4) {
    size_t i = (size_t)blockIdx.x * blockDim.x + threadIdx.x;
    if (i >= n4) return;
    float4 v = ((const float4*)src)[i];
    ushort4 hv = make_ushort4(__half_as_ushort(__float2half_rn(v.x)),
                              __half_as_ushort(__float2half_rn(v.y)),
                              __half_as_ushort(__float2half_rn(v.z)),
                              __half_as_ushort(__float2half_rn(v.w)));
    *(ushort4*)(dst + 4 * i) = hv;
}

// ------------------------------ gating -------------------------------------

__global__ void gate_kernel(const float* __restrict__ x,
                            const float* __restrict__ gw, int T) {
    int warp = (blockIdx.x * blockDim.x + threadIdx.x) >> 5;
    int lane = threadIdx.x & 31;
    if (warp >= T) return;
    const float* xr = x + (size_t)warp * HID;

    double acc[NEXP];
#pragma unroll
    for (int e = 0; e < NEXP; e++) acc[e] = 0.0;
    for (int i = lane; i < HID; i += 32) {
        float xv = xr[i];
#pragma unroll
        for (int e = 0; e < NEXP; e++)
            acc[e] += (double)xv * (double)gw[e * HID + i];
    }
#pragma unroll
    for (int e = 0; e < NEXP; e++) {
#pragma unroll
        for (int o = 16; o > 0; o >>= 1)
            acc[e] += __shfl_down_sync(0xffffffffu, acc[e], o);
    }
    if (lane == 0) {
        float v[NEXP];
#pragma unroll
        for (int e = 0; e < NEXP; e++) v[e] = (float)acc[e];
        float bv = -1e30f, sv = -1e30f;
        int bi = 0, si = 0;
#pragma unroll
        for (int e = 0; e < NEXP; e++) {
            float val = v[e];
            if (val > bv) { sv = bv; si = bi; bv = val; bi = e; }
            else if (val > sv) { sv = val; si = e; }
        }
        float e1 = expf(sv - bv);
        float s = 1.0f + e1;
        d_slot_w[2 * warp + 0] = 1.0f / s;
        d_slot_w[2 * warp + 1] = e1 / s;
        int p0 = atomicAdd(&d_counts[bi], 1);
        d_slot_list[bi * TMAX + p0] = 2 * warp;
        int p1 = atomicAdd(&d_counts[si], 1);
        d_slot_list[si * TMAX + p1] = 2 * warp + 1;
    }
}

// ----------------------------- HMMA GEMM -----------------------------------
// CTA tile 128(M) x 256(N), BK=64 fp16 (128 B rows, xor-8 swizzle).
// 8 warps of 64x64. A: 1 or 2 fp16 planes; B: 1 fp16 plane.

#define BM 128
#define BN 256
#define BK 64

#define SM_BUF 1024

template <int KDIM, int NDIM, bool FFN1>
__global__ void __launch_bounds__(256, 1)
moe_gemm_mma(const float* __restrict__ Bv)   // bias [NEXP][NDIM]
{
    constexpr int APL   = FFN1 ? 2 : 1;        // A planes
    constexpr int AREG  = 16384;               // bytes per A plane (128*128)
    constexpr int BOFF  = APL * AREG;          // B region offset in buffer
    constexpr int BUFSZ = BOFF + 32768;        // + 256 rows * 128 B
    constexpr int NC    = KDIM / BK;

    const int e   = blockIdx.z;
    const int cnt = d_counts[e];
    const int r0  = blockIdx.y * BM;
    if (r0 >= cnt) return;
    const int n0  = blockIdx.x * BN;

    const __half* __restrict__ Wbase = FFN1 ? d_w1h : d_w2h;

    extern __shared__ __align__(128) char smem[];
    const uint32_t sb = smem_u32(smem);
    const int tid = threadIdx.x;

    int* Srow = (int*)smem;
    if (tid < BM) {
        int idx = r0 + tid;
        Srow[tid] = (idx < cnt) ? d_slot_list[e * TMAX + idx] : -1;
    }
    __syncthreads();

    // ---- loader precompute ------------------------------------------------
    // B: thread tid -> row tid (256 rows), 8 x 16B chunks (one 128B line).
    const uint32_t b_dst = BOFF + (uint32_t)tid * 128u;
    const int      brx   = tid & 7;
    const __half*  bptr  = Wbase + ((size_t)e * NDIM + n0 + tid) * KDIM;

    // A: FFN1: plane = tid>>7, row = tid&127, 8 chunks.
    //    FFN2: row = tid>>1, 4 chunks starting at (tid&1)*4.
    int arow_ld, ach0, anch;
    uint32_t a_dst;
    const __half* aptr;
    if (FFN1) {
        const int pl = tid >> 7;
        arow_ld = tid & 127; ach0 = 0; anch = 8;
        a_dst = (uint32_t)pl * AREG + (uint32_t)arow_ld * 128u;
        int s = Srow[arow_ld];
        int tok = (s < 0) ? 0 : (s >> 1);
        aptr = d_xs + (size_t)pl * XOFF + (size_t)tok * KDIM;
    } else {
        arow_ld = tid >> 1; ach0 = (tid & 1) * 4; anch = 4;
        a_dst = (uint32_t)arow_ld * 128u;
        int s = Srow[arow_ld];
        aptr = d_hs + (size_t)(s < 0 ? 0 : s) * KDIM;
    }
    const int arx = arow_ld & 7;

    auto load_chunk = [&](int c, uint32_t dbuf) {
        const int koff = c * BK;
#pragma unroll
        for (int i = 0; i < anch; i++) {
            int ch = ach0 + i;
            cp16(dbuf + a_dst + (uint32_t)((ch ^ arx) << 4),
                 aptr + koff + ch * 8);
        }
#pragma unroll
        for (int ch = 0; ch < 8; ch++) {
            cp16(dbuf + b_dst + (uint32_t)((ch ^ brx) << 4),
                 bptr + koff + ch * 8);
        }
    };

    // ---- compute precompute ----------------------------------------------
    const int wid = tid >> 5, l = tid & 31;
    const int wm = wid >> 2;           // 0..1  M half
    const int wn = wid & 3;            // 0..3  N quarter
    const int g  = l >> 2, tg = l & 3;

    const int arow0 = wm * 64 + (l & 15);
    const uint32_t a_rowoff = (uint32_t)arow0 * 128u;
    const int axr = arow0 & 7;
    const int a_chsel = l >> 4;

    const int brow0 = wn * 64 + ((l >> 4) << 3) + (l & 7);
    const uint32_t b_rowoff = (uint32_t)brow0 * 128u;
    const int bxr = brow0 & 7;
    const int b_chsel = (l >> 3) & 1;

    float acc[4][8][4];
#pragma unroll
    for (int a = 0; a < 4; a++)
#pragma unroll
        for (int b = 0; b < 8; b++)
#pragma unroll
            for (int q = 0; q < 4; q++) acc[a][b][q] = 0.0f;

    load_chunk(0, sb + SM_BUF);
    CP_COMMIT();

    for (int c = 0; c < NC; c++) {
        const uint32_t sbuf = sb + SM_BUF + (uint32_t)(c & 1) * BUFSZ;
        if (c + 1 < NC) {
            load_chunk(c + 1, sb + SM_BUF + (uint32_t)((c + 1) & 1) * BUFSZ);
            CP_COMMIT();
            CP_WAIT(1);
        } else {
            CP_WAIT(0);
        }
        __syncthreads();

#pragma unroll
        for (int ks = 0; ks < BK / 16; ks++) {
            uint32_t ah[4][4], al[4][4];
            const uint32_t aoff =
                (uint32_t)(((2 * ks + a_chsel) ^ axr) << 4);
#pragma unroll
            for (int mi = 0; mi < 4; mi++) {
                uint32_t addr = sbuf + a_rowoff + (uint32_t)mi * 2048u + aoff;
                ldm_x4(ah[mi], addr);
                if (FFN1) ldm_x4(al[mi], addr + AREG);
            }
            const uint32_t boff =
                (uint32_t)(((2 * ks + b_chsel) ^ bxr) << 4);
#pragma unroll
            for (int jp = 0; jp < 4; jp++) {
                uint32_t baddr = sbuf + BOFF + b_rowoff +
                                 (uint32_t)jp * 2048u + boff;
                uint32_t bh[4];
                ldm_x4(bh, baddr);
#pragma unroll
                for (int mi = 0; mi < 4; mi++) {
                    mma16816(acc[mi][2 * jp],     ah[mi], bh[0], bh[1]);
                    mma16816(acc[mi][2 * jp + 1], ah[mi], bh[2], bh[3]);
                    if (FFN1) {
                        mma16816(acc[mi][2 * jp],     al[mi], bh[0], bh[1]);
                        mma16816(acc[mi][2 * jp + 1], al[mi], bh[2], bh[3]);
                    }
                }
            }
        }
        __syncthreads();
    }

    // ---- epilogue ---------------------------------------------------------
    const float* bias = Bv + (size_t)e * NDIM;
#pragma unroll
    for (int mi = 0; mi < 4; mi++) {
        const int lr0 = wm * 64 + mi * 16 + g;
        const int slotA = Srow[lr0];
        const int slotB = Srow[lr0 + 8];
#pragma unroll
        for (int nj = 0; nj < 8; nj++) {
            const int col = n0 + wn * 64 + nj * 8 + 2 * tg;
            const float b0 = bias[col], b1 = bias[col + 1];
            if (FFN1) {
                if (slotA >= 0) {
                    float v0 = acc[mi][nj][0] + b0;
                    float v1 = acc[mi][nj][1] + b1;
                    v0 = 0.5f * v0 * (1.0f + erff(v0 * 0.7071067811865475f));
                    v1 = 0.5f * v1 * (1.0f + erff(v1 * 0.7071067811865475f));
                    *(__half2*)(d_hs + (size_t)slotA * INTER + col) =
                        __floats2half2_rn(v0, v1);
                }
                if (slotB >= 0) {
                    float v0 = acc[mi][nj][2] + b0;
                    float v1 = acc[mi][nj][3] + b1;
                    v0 = 0.5f * v0 * (1.0f + erff(v0 * 0.7071067811865475f));
                    v1 = 0.5f * v1 * (1.0f + erff(v1 * 0.7071067811865475f));
                    *(__half2*)(d_hs + (size_t)slotB * INTER + col) =
                        __floats2half2_rn(v0, v1);
                }
            } else {
                if (slotA >= 0) {
                    float wmul = d_slot_w[slotA];
                    float2 o;
                    o.x = (acc[mi][nj][0] + b0) * wmul;
                    o.y = (acc[mi][nj][1] + b1) * wmul;
                    *(float2*)(d_y + (size_t)slotA * HID + col) = o;
                }
                if (slotB >= 0) {
                    float wmul = d_slot_w[slotB];
                    float2 o;
                    o.x = (acc[mi][nj][2] + b0) * wmul;
                    o.y = (acc[mi][nj][3] + b1) * wmul;
                    *(float2*)(d_y + (size_t)slotB * HID + col) = o;
                }
            }
        }
    }
}

// ------------------------------ combine ------------------------------------

__global__ void combine_kernel(float* __restrict__ out, int T) {
    int i = blockIdx.x * blockDim.x + threadIdx.x;
    int total = T * (HID / 4);
    if (i >= total) return;
    int h4 = i & (HID / 4 - 1);
    int t  = i >> 8;
    const float4* y4 = (const float4*)d_y;
    float4 a = y4[(size_t)(2 * t) * (HID / 4) + h4];
    float4 b = y4[(size_t)(2 * t + 1) * (HID / 4) + h4];
    float4 r;
    r.x = a.x + b.x; r.y = a.y + b.y; r.z = a.z + b.z; r.w = a.w + b.w;
    ((float4*)out)[i] = r;
}

// ------------------------------- launch ------------------------------------

extern "C" void kernel_launch(void* const* d_in, const int* in_sizes, int n_in,
                              void* d_out, int out_size) {
    const float* x  = (const float*)d_in[0];
    const float* gw = (const float*)d_in[1];
    const float* W1 = (const float*)d_in[2];
    const float* b1 = (const float*)d_in[3];
    const float* W2 = (const float*)d_in[4];
    const float* b2 = (const float*)d_in[5];
    float* out = (float*)d_out;

    int T = in_sizes[0] / HID;

    constexpr int SMEM1 = SM_BUF + 2 * (2 * 16384 + 32768);   // 132096
    constexpr int SMEM2 = SM_BUF + 2 * (1 * 16384 + 32768);   //  99328
    cudaFuncSetAttribute(moe_gemm_mma<HID, INTER, true>,
                         cudaFuncAttributeMaxDynamicSharedMemorySize, SMEM1);
    cudaFuncSetAttribute(moe_gemm_mma<INTER, HID, false>,
                         cudaFuncAttributeMaxDynamicSharedMemorySize, SMEM2);

    __half* dw1; cudaGetSymbolAddress((void**)&dw1, d_w1h);
    __half* dw2; cudaGetSymbolAddress((void**)&dw2, d_w2h);

    // launch 0: x split (+ count zeroing)
    size_t nx4 = (size_t)T * HID / 4;
    split_x_kernel<<<(unsigned)((nx4 + 255) / 256), 256>>>(x, nx4);
    // launches 1,2: weight splits
    size_t nw4 = WCNT / 4;
    split_w_kernel<<<(unsigned)((nw4 + 255) / 256), 256>>>(W1, dw1, nw4);
    split_w_kernel<<<(unsigned)((nw4 + 255) / 256), 256>>>(W2, dw2, nw4);
    // launch 3: gating
    gate_kernel<<<(T + 7) / 8, 256>>>(x, gw, T);

    int mtiles = (T + BM - 1) / BM;
    // launch 4: GEMM1
    dim3 g1(INTER / BN, mtiles, NEXP);
    moe_gemm_mma<HID, INTER, true><<<g1, 256, SMEM1>>>(b1);
    // launch 5: GEMM2  (ncu -s 5 target)
    dim3 g2(HID / BN, mtiles, NEXP);
    moe_gemm_mma<INTER, HID, false><<<g2, 256, SMEM2>>>(b2);
    // launch 6: combine
    combine_kernel<<<(T * (HID / 4) + 255) / 256, 256>>>(out, T);
}

// round 7
// speedup vs baseline: 5.6438x; 1.3110x over previous
#include <cuda_runtime.h>
#include <cuda_bf16.h>
#include <cuda_fp16.h>
#include <math.h>
#include <stdint.h>

// ---------------------------------------------------------------------------
// MoE FFN top-2/8, H=1024, I=4096, T<=8192, fp32 in/out.
// R6: single-plane fp16 HMMA for both GEMMs (MMA-issue bound -> minimize
// MMA instruction count).
//   x,W1,W2 -> fp16 single plane; h -> fp16 single plane.
//   GEMM1: x @ W1^T + b1, GELU -> h fp16      (1 MMA pass)
//   GEMM2: h @ W2^T + b2, *slot_w -> d_y fp32 (1 MMA pass)
// Launch order: split_x(0), split_w1(1), gate(2), gemm1(3 = ncu target),
//               split_w2(4), gemm2(5), combine(6).
// ---------------------------------------------------------------------------

#define HID   1024
#define INTER 4096
#define NEXP  8
#define TMAX  8192
#define NSLOT (2 * TMAX)

#define WCNT ((size_t)NEXP * (size_t)INTER * (size_t)HID)
#define XOFF ((size_t)TMAX * (size_t)HID)
#define HOFF ((size_t)NSLOT * (size_t)INTER)

__device__ __half d_xs[XOFF];         // x fp16
__device__ __half d_w1h[WCNT];        // W1 fp16
__device__ __half d_w2h[WCNT];        // W2 fp16
__device__ __half d_hs[HOFF];         // h fp16
__device__ float  d_y[(size_t)NSLOT * (size_t)HID];
__device__ float  d_slot_w[NSLOT];
__device__ int    d_slot_list[NEXP * TMAX];
__device__ int    d_counts[NEXP];

// ------------------------------ PTX helpers --------------------------------

__device__ __forceinline__ uint32_t smem_u32(const void* p) {
    uint32_t a;
    asm("{ .reg .u64 t; cvta.to.shared.u64 t, %1; cvt.u32.u64 %0, t; }"
        : "=r"(a) : "l"(p));
    return a;
}

__device__ __forceinline__ void cp16(uint32_t saddr, const void* g) {
    asm volatile("cp.async.cg.shared.global [%0], [%1], 16;"
                 :: "r"(saddr), "l"(g));
}
#define CP_COMMIT() asm volatile("cp.async.commit_group;" ::: "memory")
#define CP_WAIT(N)  asm volatile("cp.async.wait_group %0;" :: "n"(N) : "memory")

__device__ __forceinline__ void ldm_x4(uint32_t* r, uint32_t addr) {
    asm volatile("ldmatrix.sync.aligned.m8n8.x4.shared.b16 {%0,%1,%2,%3}, [%4];"
                 : "=r"(r[0]), "=r"(r[1]), "=r"(r[2]), "=r"(r[3]) : "r"(addr));
}

__device__ __forceinline__ void mma16816(float* c, const uint32_t* a,
                                         uint32_t b0, uint32_t b1) {
    asm volatile(
        "mma.sync.aligned.m16n8k16.row.col.f32.f16.f16.f32 "
        "{%0,%1,%2,%3}, {%4,%5,%6,%7}, {%8,%9}, {%0,%1,%2,%3};"
        : "+f"(c[0]), "+f"(c[1]), "+f"(c[2]), "+f"(c[3])
        : "r"(a[0]), "r"(a[1]), "r"(a[2]), "r"(a[3]), "r"(b0), "r"(b1));
}

// ---------------------------- split kernels --------------------------------

// fp32 -> fp16 single plane; optionally zero expert counts (block 0).
__global__ void split_kernel(const float* __restrict__ src,
                             __half* __restrict__ dst, size_t n4,
                             int zero_counts) {
    if (zero_counts && blockIdx.x == 0 && threadIdx.x < NEXP)
        d_counts[threadIdx.x] = 0;
    size_t i = (size_t)blockIdx.x * blockDim.x + threadIdx.x;
    if (i >= n4) return;
    float4 v = ((const float4*)src)[i];
    ushort4 hv = make_ushort4(__half_as_ushort(__float2half_rn(v.x)),
                              __half_as_ushort(__float2half_rn(v.y)),
                              __half_as_ushort(__float2half_rn(v.z)),
                              __half_as_ushort(__float2half_rn(v.w)));
    *(ushort4*)(dst + 4 * i) = hv;
}

// ------------------------------ gating -------------------------------------

__global__ void gate_kernel(const float* __restrict__ x,
                            const float* __restrict__ gw, int T) {
    int warp = (blockIdx.x * blockDim.x + threadIdx.x) >> 5;
    int lane = threadIdx.x & 31;
    if (warp >= T) return;
    const float* xr = x + (size_t)warp * HID;

    double acc[NEXP];
#pragma unroll
    for (int e = 0; e < NEXP; e++) acc[e] = 0.0;
#pragma unroll 4
    for (int i = lane; i < HID; i += 32) {
        float xv = xr[i];
#pragma unroll
        for (int e = 0; e < NEXP; e++)
            acc[e] += (double)xv * (double)gw[e * HID + i];
    }
#pragma unroll
    for (int e = 0; e < NEXP; e++) {
#pragma unroll
        for (int o = 16; o > 0; o >>= 1)
            acc[e] += __shfl_down_sync(0xffffffffu, acc[e], o);
    }
    if (lane == 0) {
        float v[NEXP];
#pragma unroll
        for (int e = 0; e < NEXP; e++) v[e] = (float)acc[e];
        float bv = -1e30f, sv = -1e30f;
        int bi = 0, si = 0;
#pragma unroll
        for (int e = 0; e < NEXP; e++) {
            float val = v[e];
            if (val > bv) { sv = bv; si = bi; bv = val; bi = e; }
            else if (val > sv) { sv = val; si = e; }
        }
        float e1 = expf(sv - bv);
        float s = 1.0f + e1;
        d_slot_w[2 * warp + 0] = 1.0f / s;
        d_slot_w[2 * warp + 1] = e1 / s;
        int p0 = atomicAdd(&d_counts[bi], 1);
        d_slot_list[bi * TMAX + p0] = 2 * warp;
        int p1 = atomicAdd(&d_counts[si], 1);
        d_slot_list[si * TMAX + p1] = 2 * warp + 1;
    }
}

// ----------------------------- HMMA GEMM -----------------------------------
// CTA tile 128(M) x 256(N), BK=64 fp16 (128 B rows, xor-8 swizzle).
// 8 warps of 64x64. Single fp16 plane for A and B.

#define BM 128
#define BN 256
#define BK 64

#define SM_BUF 1024
#define AREG   16384                  // A region: 128 rows * 128 B
#define BOFF   AREG                   // B region offset
#define BUFSZ  (AREG + 32768)         // + 256 rows * 128 B
#define SMEM_TOTAL (SM_BUF + 2 * BUFSZ)   // 99328 B

template <int KDIM, int NDIM, bool FFN1>
__global__ void __launch_bounds__(256, 1)
moe_gemm_mma(const float* __restrict__ Bv)   // bias [NEXP][NDIM]
{
    constexpr int NC = KDIM / BK;

    const int e   = blockIdx.z;
    const int cnt = d_counts[e];
    const int r0  = blockIdx.y * BM;
    if (r0 >= cnt) return;
    const int n0  = blockIdx.x * BN;

    const __half* __restrict__ Wbase = FFN1 ? d_w1h : d_w2h;
    const __half* __restrict__ Abase = FFN1 ? d_xs : d_hs;

    extern __shared__ __align__(128) char smem[];
    const uint32_t sb = smem_u32(smem);
    const int tid = threadIdx.x;

    int* Srow = (int*)smem;
    if (tid < BM) {
        int idx = r0 + tid;
        Srow[tid] = (idx < cnt) ? d_slot_list[e * TMAX + idx] : -1;
    }
    __syncthreads();

    // ---- loader precompute ------------------------------------------------
    // B: thread tid -> row tid (256 rows), 8 x 16B chunks (one 128B line).
    const uint32_t b_dst = BOFF + (uint32_t)tid * 128u;
    const int      brx   = tid & 7;
    const __half*  bptr  = Wbase + ((size_t)e * NDIM + n0 + tid) * KDIM;

    // A: row = tid>>1, 4 chunks starting at (tid&1)*4.
    const int arow_ld = tid >> 1;
    const int ach0    = (tid & 1) * 4;
    const uint32_t a_dst = (uint32_t)arow_ld * 128u;
    const int arx = arow_ld & 7;
    int s_ld = Srow[arow_ld];
    const __half* aptr;
    if (FFN1) {
        int tok = (s_ld < 0) ? 0 : (s_ld >> 1);
        aptr = Abase + (size_t)tok * KDIM;
    } else {
        aptr = Abase + (size_t)(s_ld < 0 ? 0 : s_ld) * KDIM;
    }

    auto load_chunk = [&](int c, uint32_t dbuf) {
        const int koff = c * BK;
#pragma unroll
        for (int i = 0; i < 4; i++) {
            int ch = ach0 + i;
            cp16(dbuf + a_dst + (uint32_t)((ch ^ arx) << 4),
                 aptr + koff + ch * 8);
        }
#pragma unroll
        for (int ch = 0; ch < 8; ch++) {
            cp16(dbuf + b_dst + (uint32_t)((ch ^ brx) << 4),
                 bptr + koff + ch * 8);
        }
    };

    // ---- compute precompute ----------------------------------------------
    const int wid = tid >> 5, l = tid & 31;
    const int wm = wid >> 2;           // 0..1  M half
    const int wn = wid & 3;            // 0..3  N quarter
    const int g  = l >> 2, tg = l & 3;

    const int arow0 = wm * 64 + (l & 15);
    const uint32_t a_rowoff = (uint32_t)arow0 * 128u;
    const int axr = arow0 & 7;
    const int a_chsel = l >> 4;

    const int brow0 = wn * 64 + ((l >> 4) << 3) + (l & 7);
    const uint32_t b_rowoff = (uint32_t)brow0 * 128u;
    const int bxr = brow0 & 7;
    const int b_chsel = (l >> 3) & 1;

    float acc[4][8][4];
#pragma unroll
    for (int a = 0; a < 4; a++)
#pragma unroll
        for (int b = 0; b < 8; b++)
#pragma unroll
            for (int q = 0; q < 4; q++) acc[a][b][q] = 0.0f;

    load_chunk(0, sb + SM_BUF);
    CP_COMMIT();

    for (int c = 0; c < NC; c++) {
        const uint32_t sbuf = sb + SM_BUF + (uint32_t)(c & 1) * BUFSZ;
        if (c + 1 < NC) {
            load_chunk(c + 1, sb + SM_BUF + (uint32_t)((c + 1) & 1) * BUFSZ);
            CP_COMMIT();
            CP_WAIT(1);
        } else {
            CP_WAIT(0);
        }
        __syncthreads();

#pragma unroll
        for (int ks = 0; ks < BK / 16; ks++) {
            uint32_t ah[4][4];
            const uint32_t aoff =
                (uint32_t)(((2 * ks + a_chsel) ^ axr) << 4);
#pragma unroll
            for (int mi = 0; mi < 4; mi++) {
                uint32_t addr = sbuf + a_rowoff + (uint32_t)mi * 2048u + aoff;
                ldm_x4(ah[mi], addr);
            }
            const uint32_t boff =
                (uint32_t)(((2 * ks + b_chsel) ^ bxr) << 4);
#pragma unroll
            for (int jp = 0; jp < 4; jp++) {
                uint32_t baddr = sbuf + BOFF + b_rowoff +
                                 (uint32_t)jp * 2048u + boff;
                uint32_t bh[4];
                ldm_x4(bh, baddr);
#pragma unroll
                for (int mi = 0; mi < 4; mi++) {
                    mma16816(acc[mi][2 * jp],     ah[mi], bh[0], bh[1]);
                    mma16816(acc[mi][2 * jp + 1], ah[mi], bh[2], bh[3]);
                }
            }
        }
        __syncthreads();
    }

    // ---- epilogue ---------------------------------------------------------
    const float* bias = Bv + (size_t)e * NDIM;
#pragma unroll
    for (int mi = 0; mi < 4; mi++) {
        const int lr0 = wm * 64 + mi * 16 + g;
        const int slotA = Srow[lr0];
        const int slotB = Srow[lr0 + 8];
#pragma unroll
        for (int nj = 0; nj < 8; nj++) {
            const int col = n0 + wn * 64 + nj * 8 + 2 * tg;
            const float b0 = bias[col], b1 = bias[col + 1];
            if (FFN1) {
                if (slotA >= 0) {
                    float v0 = acc[mi][nj][0] + b0;
                    float v1 = acc[mi][nj][1] + b1;
                    v0 = 0.5f * v0 * (1.0f + erff(v0 * 0.7071067811865475f));
                    v1 = 0.5f * v1 * (1.0f + erff(v1 * 0.7071067811865475f));
                    *(__half2*)(d_hs + (size_t)slotA * INTER + col) =
                        __floats2half2_rn(v0, v1);
                }
                if (slotB >= 0) {
                    float v0 = acc[mi][nj][2] + b0;
                    float v1 = acc[mi][nj][3] + b1;
                    v0 = 0.5f * v0 * (1.0f + erff(v0 * 0.7071067811865475f));
                    v1 = 0.5f * v1 * (1.0f + erff(v1 * 0.7071067811865475f));
                    *(__half2*)(d_hs + (size_t)slotB * INTER + col) =
                        __floats2half2_rn(v0, v1);
                }
            } else {
                if (slotA >= 0) {
                    float wmul = d_slot_w[slotA];
                    float2 o;
                    o.x = (acc[mi][nj][0] + b0) * wmul;
                    o.y = (acc[mi][nj][1] + b1) * wmul;
                    *(float2*)(d_y + (size_t)slotA * HID + col) = o;
                }
                if (slotB >= 0) {
                    float wmul = d_slot_w[slotB];
                    float2 o;
                    o.x = (acc[mi][nj][2] + b0) * wmul;
                    o.y = (acc[mi][nj][3] + b1) * wmul;
                    *(float2*)(d_y + (size_t)slotB * HID + col) = o;
                }
            }
        }
    }
}

// ------------------------------ combine ------------------------------------

__global__ void combine_kernel(float* __restrict__ out, int T) {
    int i = blockIdx.x * blockDim.x + threadIdx.x;
    int total = T * (HID / 4);
    if (i >= total) return;
    int h4 = i & (HID / 4 - 1);
    int t  = i >> 8;
    const float4* y4 = (const float4*)d_y;
    float4 a = y4[(size_t)(2 * t) * (HID / 4) + h4];
    float4 b = y4[(size_t)(2 * t + 1) * (HID / 4) + h4];
    float4 r;
    r.x = a.x + b.x; r.y = a.y + b.y; r.z = a.z + b.z; r.w = a.w + b.w;
    ((float4*)out)[i] = r;
}

// ------------------------------- launch ------------------------------------

extern "C" void kernel_launch(void* const* d_in, const int* in_sizes, int n_in,
                              void* d_out, int out_size) {
    const float* x  = (const float*)d_in[0];
    const float* gw = (const float*)d_in[1];
    const float* W1 = (const float*)d_in[2];
    const float* b1 = (const float*)d_in[3];
    const float* W2 = (const float*)d_in[4];
    const float* b2 = (const float*)d_in[5];
    float* out = (float*)d_out;

    int T = in_sizes[0] / HID;

    cudaFuncSetAttribute(moe_gemm_mma<HID, INTER, true>,
                         cudaFuncAttributeMaxDynamicSharedMemorySize,
                         SMEM_TOTAL);
    cudaFuncSetAttribute(moe_gemm_mma<INTER, HID, false>,
                         cudaFuncAttributeMaxDynamicSharedMemorySize,
                         SMEM_TOTAL);

    __half* dxs; cudaGetSymbolAddress((void**)&dxs, d_xs);
    __half* dw1; cudaGetSymbolAddress((void**)&dw1, d_w1h);
    __half* dw2; cudaGetSymbolAddress((void**)&dw2, d_w2h);

    size_t nx4 = (size_t)T * HID / 4;
    size_t nw4 = WCNT / 4;
    int mtiles = (T + BM - 1) / BM;

    // launch 0: x -> fp16 (+ zero counts)
    split_kernel<<<(unsigned)((nx4 + 255) / 256), 256>>>(x, dxs, nx4, 1);
    // launch 1: W1 -> fp16
    split_kernel<<<(unsigned)((nw4 + 255) / 256), 256>>>(W1, dw1, nw4, 0);
    // launch 2: gating
    gate_kernel<<<(T + 7) / 8, 256>>>(x, gw, T);
    // launch 3: GEMM1  (ncu target)
    dim3 g1(INTER / BN, mtiles, NEXP);
    moe_gemm_mma<HID, INTER, true><<<g1, 256, SMEM_TOTAL>>>(b1);
    // launch 4: W2 -> fp16
    split_kernel<<<(unsigned)((nw4 + 255) / 256), 256>>>(W2, dw2, nw4, 0);
    // launch 5: GEMM2
    dim3 g2(HID / BN, mtiles, NEXP);
    moe_gemm_mma<INTER, HID, false><<<g2, 256, SMEM_TOTAL>>>(b2);
    // launch 6: combine
    combine_kernel<<<(T * (HID / 4) + 255) / 256, 256>>>(out, T);
}

// round 9
// speedup vs baseline: 5.7179x; 1.0131x over previous
#include <cuda_runtime.h>
#include <cuda_bf16.h>
#include <cuda_fp16.h>
#include <math.h>
#include <stdint.h>

// ---------------------------------------------------------------------------
// MoE FFN top-2/8, H=1024, I=4096, T<=8192, fp32 in/out.
// R9 (= R8 resubmit; R8 hit a broker infra failure, no kernel signal):
// single-plane fp16 HMMA, depth-3 cp.async pipeline (4 smem buffers),
// ONE __syncthreads per K-chunk (latency-bound fix; occupancy is reg-pinned
// at 1 CTA/SM so we minimize per-chunk stall bubbles instead).
// Launch order: split_x(0), split_w1(1), gate(2), gemm1(3 = ncu target),
//               split_w2(4), gemm2(5), combine(6).
// ---------------------------------------------------------------------------

#define HID   1024
#define INTER 4096
#define NEXP  8
#define TMAX  8192
#define NSLOT (2 * TMAX)

#define WCNT ((size_t)NEXP * (size_t)INTER * (size_t)HID)
#define XOFF ((size_t)TMAX * (size_t)HID)
#define HOFF ((size_t)NSLOT * (size_t)INTER)

__device__ __half d_xs[XOFF];         // x fp16
__device__ __half d_w1h[WCNT];        // W1 fp16
__device__ __half d_w2h[WCNT];        // W2 fp16
__device__ __half d_hs[HOFF];         // h fp16
__device__ float  d_y[(size_t)NSLOT * (size_t)HID];
__device__ float  d_slot_w[NSLOT];
__device__ int    d_slot_list[NEXP * TMAX];
__device__ int    d_counts[NEXP];

// ------------------------------ PTX helpers --------------------------------

__device__ __forceinline__ uint32_t smem_u32(const void* p) {
    uint32_t a;
    asm("{ .reg .u64 t; cvta.to.shared.u64 t, %1; cvt.u32.u64 %0, t; }"
        : "=r"(a) : "l"(p));
    return a;
}

__device__ __forceinline__ void cp16(uint32_t saddr, const void* g) {
    asm volatile("cp.async.cg.shared.global [%0], [%1], 16;"
                 :: "r"(saddr), "l"(g));
}
#define CP_COMMIT() asm volatile("cp.async.commit_group;" ::: "memory")
#define CP_WAIT(N)  asm volatile("cp.async.wait_group %0;" :: "n"(N) : "memory")

__device__ __forceinline__ void ldm_x4(uint32_t* r, uint32_t addr) {
    asm volatile("ldmatrix.sync.aligned.m8n8.x4.shared.b16 {%0,%1,%2,%3}, [%4];"
                 : "=r"(r[0]), "=r"(r[1]), "=r"(r[2]), "=r"(r[3]) : "r"(addr));
}

__device__ __forceinline__ void mma16816(float* c, const uint32_t* a,
                                         uint32_t b0, uint32_t b1) {
    asm volatile(
        "mma.sync.aligned.m16n8k16.row.col.f32.f16.f16.f32 "
        "{%0,%1,%2,%3}, {%4,%5,%6,%7}, {%8,%9}, {%0,%1,%2,%3};"
        : "+f"(c[0]), "+f"(c[1]), "+f"(c[2]), "+f"(c[3])
        : "r"(a[0]), "r"(a[1]), "r"(a[2]), "r"(a[3]), "r"(b0), "r"(b1));
}

// ---------------------------- split kernels --------------------------------

__global__ void split_kernel(const float* __restrict__ src,
                             __half* __restrict__ dst, size_t n4,
                             int zero_counts) {
    if (zero_counts && blockIdx.x == 0 && threadIdx.x < NEXP)
        d_counts[threadIdx.x] = 0;
    size_t i = (size_t)blockIdx.x * blockDim.x + threadIdx.x;
    if (i >= n4) return;
    float4 v = ((const float4*)src)[i];
    ushort4 hv = make_ushort4(__half_as_ushort(__float2half_rn(v.x)),
                              __half_as_ushort(__float2half_rn(v.y)),
                              __half_as_ushort(__float2half_rn(v.z)),
                              __half_as_ushort(__float2half_rn(v.w)));
    *(ushort4*)(dst + 4 * i) = hv;
}

// ------------------------------ gating -------------------------------------

__global__ void gate_kernel(const float* __restrict__ x,
                            const float* __restrict__ gw, int T) {
    int warp = (blockIdx.x * blockDim.x + threadIdx.x) >> 5;
    int lane = threadIdx.x & 31;
    if (warp >= T) return;
    const float* xr = x + (size_t)warp * HID;

    double acc[NEXP];
#pragma unroll
    for (int e = 0; e < NEXP; e++) acc[e] = 0.0;
#pragma unroll 4
    for (int i = lane; i < HID; i += 32) {
        float xv = xr[i];
#pragma unroll
        for (int e = 0; e < NEXP; e++)
            acc[e] += (double)xv * (double)gw[e * HID + i];
    }
#pragma unroll
    for (int e = 0; e < NEXP; e++) {
#pragma unroll
        for (int o = 16; o > 0; o >>= 1)
            acc[e] += __shfl_down_sync(0xffffffffu, acc[e], o);
    }
    if (lane == 0) {
        float v[NEXP];
#pragma unroll
        for (int e = 0; e < NEXP; e++) v[e] = (float)acc[e];
        float bv = -1e30f, sv = -1e30f;
        int bi = 0, si = 0;
#pragma unroll
        for (int e = 0; e < NEXP; e++) {
            float val = v[e];
            if (val > bv) { sv = bv; si = bi; bv = val; bi = e; }
            else if (val > sv) { sv = val; si = e; }
        }
        float e1 = expf(sv - bv);
        float s = 1.0f + e1;
        d_slot_w[2 * warp + 0] = 1.0f / s;
        d_slot_w[2 * warp + 1] = e1 / s;
        int p0 = atomicAdd(&d_counts[bi], 1);
        d_slot_list[bi * TMAX + p0] = 2 * warp;
        int p1 = atomicAdd(&d_counts[si], 1);
        d_slot_list[si * TMAX + p1] = 2 * warp + 1;
    }
}

// ----------------------------- HMMA GEMM -----------------------------------
// CTA tile 128(M) x 256(N), BK=64 fp16 (128 B rows, xor-8 swizzle).
// 8 warps of 64x64. 4 smem buffers, cp.async depth 3, 1 barrier per chunk.

#define BM 128
#define BN 256
#define BK 64

#define SM_BUF 1024
#define AREG   16384                  // A region: 128 rows * 128 B
#define BOFF   AREG                   // B region offset
#define BUFSZ  (AREG + 32768)         // 49152: + 256 rows * 128 B
#define NBUF   4
#define SMEM_TOTAL (SM_BUF + NBUF * BUFSZ)   // 197632 B = 193 KB

template <int KDIM, int NDIM, bool FFN1>
__global__ void __launch_bounds__(256, 1)
moe_gemm_mma(const float* __restrict__ Bv)   // bias [NEXP][NDIM]
{
    constexpr int NC = KDIM / BK;     // 16 or 64 (>= 3)

    const int e   = blockIdx.z;
    const int cnt = d_counts[e];
    const int r0  = blockIdx.y * BM;
    if (r0 >= cnt) return;
    const int n0  = blockIdx.x * BN;

    const __half* __restrict__ Wbase = FFN1 ? d_w1h : d_w2h;
    const __half* __restrict__ Abase = FFN1 ? d_xs : d_hs;

    extern __shared__ __align__(128) char smem[];
    const uint32_t sb = smem_u32(smem);
    const int tid = threadIdx.x;

    int* Srow = (int*)smem;
    if (tid < BM) {
        int idx = r0 + tid;
        Srow[tid] = (idx < cnt) ? d_slot_list[e * TMAX + idx] : -1;
    }
    __syncthreads();

    // ---- loader precompute ------------------------------------------------
    const uint32_t b_dst = BOFF + (uint32_t)tid * 128u;
    const int      brx   = tid & 7;
    const __half*  bptr  = Wbase + ((size_t)e * NDIM + n0 + tid) * KDIM;

    const int arow_ld = tid >> 1;
    const int ach0    = (tid & 1) * 4;
    const uint32_t a_dst = (uint32_t)arow_ld * 128u;
    const int arx = arow_ld & 7;
    int s_ld = Srow[arow_ld];
    const __half* aptr;
    if (FFN1) {
        int tok = (s_ld < 0) ? 0 : (s_ld >> 1);
        aptr = Abase + (size_t)tok * KDIM;
    } else {
        aptr = Abase + (size_t)(s_ld < 0 ? 0 : s_ld) * KDIM;
    }

    auto load_chunk = [&](int c) {
        const uint32_t dbuf = sb + SM_BUF + (uint32_t)(c & (NBUF - 1)) * BUFSZ;
        const int koff = c * BK;
#pragma unroll
        for (int i = 0; i < 4; i++) {
            int ch = ach0 + i;
            cp16(dbuf + a_dst + (uint32_t)((ch ^ arx) << 4),
                 aptr + koff + ch * 8);
        }
#pragma unroll
        for (int ch = 0; ch < 8; ch++) {
            cp16(dbuf + b_dst + (uint32_t)((ch ^ brx) << 4),
                 bptr + koff + ch * 8);
        }
        CP_COMMIT();
    };

    // ---- compute precompute ----------------------------------------------
    const int wid = tid >> 5, l = tid & 31;
    const int wm = wid >> 2;           // 0..1  M half
    const int wn = wid & 3;            // 0..3  N quarter
    const int g  = l >> 2, tg = l & 3;

    const int arow0 = wm * 64 + (l & 15);
    const uint32_t a_rowoff = (uint32_t)arow0 * 128u;
    const int axr = arow0 & 7;
    const int a_chsel = l >> 4;

    const int brow0 = wn * 64 + ((l >> 4) << 3) + (l & 7);
    const uint32_t b_rowoff = (uint32_t)brow0 * 128u;
    const int bxr = brow0 & 7;
    const int b_chsel = (l >> 3) & 1;

    float acc[4][8][4];
#pragma unroll
    for (int a = 0; a < 4; a++)
#pragma unroll
        for (int b = 0; b < 8; b++)
#pragma unroll
            for (int q = 0; q < 4; q++) acc[a][b][q] = 0.0f;

    // depth-3 preload
    load_chunk(0);
    load_chunk(1);
    load_chunk(2);

    for (int c = 0; c < NC; c++) {
        // ensure group c landed (2 newer groups may stay in flight)
        if (c + 2 < NC)      { CP_WAIT(2); }
        else if (c + 1 < NC) { CP_WAIT(1); }
        else                 { CP_WAIT(0); }
        __syncthreads();
        // issue chunk c+3 into buffer (c+3)%4 == (c-1)%4 — its readers
        // (compute of chunk c-1) all passed the barrier above.
        if (c + 3 < NC) load_chunk(c + 3);

        const uint32_t sbuf = sb + SM_BUF +
                              (uint32_t)(c & (NBUF - 1)) * BUFSZ;
#pragma unroll
        for (int ks = 0; ks < BK / 16; ks++) {
            uint32_t ah[4][4];
            const uint32_t aoff =
                (uint32_t)(((2 * ks + a_chsel) ^ axr) << 4);
#pragma unroll
            for (int mi = 0; mi < 4; mi++) {
                uint32_t addr = sbuf + a_rowoff + (uint32_t)mi * 2048u + aoff;
                ldm_x4(ah[mi], addr);
            }
            const uint32_t boff =
                (uint32_t)(((2 * ks + b_chsel) ^ bxr) << 4);
#pragma unroll
            for (int jp = 0; jp < 4; jp++) {
                uint32_t baddr = sbuf + BOFF + b_rowoff +
                                 (uint32_t)jp * 2048u + boff;
                uint32_t bh[4];
                ldm_x4(bh, baddr);
#pragma unroll
                for (int mi = 0; mi < 4; mi++) {
                    mma16816(acc[mi][2 * jp],     ah[mi], bh[0], bh[1]);
                    mma16816(acc[mi][2 * jp + 1], ah[mi], bh[2], bh[3]);
                }
            }
        }
        // no trailing barrier: next iteration's barrier protects buffer reuse
    }

    // ---- epilogue ---------------------------------------------------------
    const float* bias = Bv + (size_t)e * NDIM;
#pragma unroll
    for (int mi = 0; mi < 4; mi++) {
        const int lr0 = wm * 64 + mi * 16 + g;
        const int slotA = Srow[lr0];
        const int slotB = Srow[lr0 + 8];
#pragma unroll
        for (int nj = 0; nj < 8; nj++) {
            const int col = n0 + wn * 64 + nj * 8 + 2 * tg;
            const float b0 = bias[col], b1 = bias[col + 1];
            if (FFN1) {
                if (slotA >= 0) {
                    float v0 = acc[mi][nj][0] + b0;
                    float v1 = acc[mi][nj][1] + b1;
                    v0 = 0.5f * v0 * (1.0f + erff(v0 * 0.7071067811865475f));
                    v1 = 0.5f * v1 * (1.0f + erff(v1 * 0.7071067811865475f));
                    *(__half2*)(d_hs + (size_t)slotA * INTER + col) =
                        __floats2half2_rn(v0, v1);
                }
                if (slotB >= 0) {
                    float v0 = acc[mi][nj][2] + b0;
                    float v1 = acc[mi][nj][3] + b1;
                    v0 = 0.5f * v0 * (1.0f + erff(v0 * 0.7071067811865475f));
                    v1 = 0.5f * v1 * (1.0f + erff(v1 * 0.7071067811865475f));
                    *(__half2*)(d_hs + (size_t)slotB * INTER + col) =
                        __floats2half2_rn(v0, v1);
                }
            } else {
                if (slotA >= 0) {
                    float wmul = d_slot_w[slotA];
                    float2 o;
                    o.x = (acc[mi][nj][0] + b0) * wmul;
                    o.y = (acc[mi][nj][1] + b1) * wmul;
                    *(float2*)(d_y + (size_t)slotA * HID + col) = o;
                }
                if (slotB >= 0) {
                    float wmul = d_slot_w[slotB];
                    float2 o;
                    o.x = (acc[mi][nj][2] + b0) * wmul;
                    o.y = (acc[mi][nj][3] + b1) * wmul;
                    *(float2*)(d_y + (size_t)slotB * HID + col) = o;
                }
            }
        }
    }
}

// ------------------------------ combine ------------------------------------

__global__ void combine_kernel(float* __restrict__ out, int T) {
    int i = blockIdx.x * blockDim.x + threadIdx.x;
    int total = T * (HID / 4);
    if (i >= total) return;
    int h4 = i & (HID / 4 - 1);
    int t  = i >> 8;
    const float4* y4 = (const float4*)d_y;
    float4 a = y4[(size_t)(2 * t) * (HID / 4) + h4];
    float4 b = y4[(size_t)(2 * t + 1) * (HID / 4) + h4];
    float4 r;
    r.x = a.x + b.x; r.y = a.y + b.y; r.z = a.z + b.z; r.w = a.w + b.w;
    ((float4*)out)[i] = r;
}

// ------------------------------- launch ------------------------------------

extern "C" void kernel_launch(void* const* d_in, const int* in_sizes, int n_in,
                              void* d_out, int out_size) {
    const float* x  = (const float*)d_in[0];
    const float* gw = (const float*)d_in[1];
    const float* W1 = (const float*)d_in[2];
    const float* b1 = (const float*)d_in[3];
    const float* W2 = (const float*)d_in[4];
    const float* b2 = (const float*)d_in[5];
    float* out = (float*)d_out;

    int T = in_sizes[0] / HID;

    cudaFuncSetAttribute(moe_gemm_mma<HID, INTER, true>,
                         cudaFuncAttributeMaxDynamicSharedMemorySize,
                         SMEM_TOTAL);
    cudaFuncSetAttribute(moe_gemm_mma<INTER, HID, false>,
                         cudaFuncAttributeMaxDynamicSharedMemorySize,
                         SMEM_TOTAL);

    __half* dxs; cudaGetSymbolAddress((void**)&dxs, d_xs);
    __half* dw1; cudaGetSymbolAddress((void**)&dw1, d_w1h);
    __half* dw2; cudaGetSymbolAddress((void**)&dw2, d_w2h);

    size_t nx4 = (size_t)T * HID / 4;
    size_t nw4 = WCNT / 4;
    int mtiles = (T + BM - 1) / BM;

    // launch 0: x -> fp16 (+ zero counts)
    split_kernel<<<(unsigned)((nx4 + 255) / 256), 256>>>(x, dxs, nx4, 1);
    // launch 1: W1 -> fp16
    split_kernel<<<(unsigned)((nw4 + 255) / 256), 256>>>(W1, dw1, nw4, 0);
    // launch 2: gating
    gate_kernel<<<(T + 7) / 8, 256>>>(x, gw, T);
    // launch 3: GEMM1  (ncu target)
    dim3 g1(INTER / BN, mtiles, NEXP);
    moe_gemm_mma<HID, INTER, true><<<g1, 256, SMEM_TOTAL>>>(b1);
    // launch 4: W2 -> fp16
    split_kernel<<<(unsigned)((nw4 + 255) / 256), 256>>>(W2, dw2, nw4, 0);
    // launch 5: GEMM2
    dim3 g2(HID / BN, mtiles, NEXP);
    moe_gemm_mma<INTER, HID, false><<<g2, 256, SMEM_TOTAL>>>(b2);
    // launch 6: combine
    combine_kernel<<<(T * (HID / 4) + 255) / 256, 256>>>(out, T);
}

// round 11
// speedup vs baseline: 7.1251x; 1.2461x over previous
#include <cuda_runtime.h>
#include <cuda_bf16.h>
#include <cuda_fp16.h>
#include <math.h>
#include <stdint.h>

// ---------------------------------------------------------------------------
// MoE FFN top-2/8, H=1024, I=4096, T<=8192, fp32 in/out.
// R11 (= R10 resubmit; R10 hit broker infra failure, no kernel signal):
// occupancy experiment. CTA tile 128x128 (warp tile 64x32, 64 acc regs)
// -> 2 CTAs/SM, 4 warps/SMSP for LDSM-latency hiding. 3-buffer cp.async
// ring, 1 barrier per chunk.
// Launch order: split_x(0), split_w1(1), gate(2), gemm1(3 = ncu target),
//               split_w2(4), gemm2(5), combine(6).
// ---------------------------------------------------------------------------

#define HID   1024
#define INTER 4096
#define NEXP  8
#define TMAX  8192
#define NSLOT (2 * TMAX)

#define WCNT ((size_t)NEXP * (size_t)INTER * (size_t)HID)
#define XOFF ((size_t)TMAX * (size_t)HID)
#define HOFF ((size_t)NSLOT * (size_t)INTER)

__device__ __half d_xs[XOFF];         // x fp16
__device__ __half d_w1h[WCNT];        // W1 fp16
__device__ __half d_w2h[WCNT];        // W2 fp16
__device__ __half d_hs[HOFF];         // h fp16
__device__ float  d_y[(size_t)NSLOT * (size_t)HID];
__device__ float  d_slot_w[NSLOT];
__device__ int    d_slot_list[NEXP * TMAX];
__device__ int    d_counts[NEXP];

// ------------------------------ PTX helpers --------------------------------

__device__ __forceinline__ uint32_t smem_u32(const void* p) {
    uint32_t a;
    asm("{ .reg .u64 t; cvta.to.shared.u64 t, %1; cvt.u32.u64 %0, t; }"
        : "=r"(a) : "l"(p));
    return a;
}

__device__ __forceinline__ void cp16(uint32_t saddr, const void* g) {
    asm volatile("cp.async.cg.shared.global [%0], [%1], 16;"
                 :: "r"(saddr), "l"(g));
}
#define CP_COMMIT() asm volatile("cp.async.commit_group;" ::: "memory")
#define CP_WAIT(N)  asm volatile("cp.async.wait_group %0;" :: "n"(N) : "memory")

__device__ __forceinline__ void ldm_x4(uint32_t* r, uint32_t addr) {
    asm volatile("ldmatrix.sync.aligned.m8n8.x4.shared.b16 {%0,%1,%2,%3}, [%4];"
                 : "=r"(r[0]), "=r"(r[1]), "=r"(r[2]), "=r"(r[3]) : "r"(addr));
}

__device__ __forceinline__ void mma16816(float* c, const uint32_t* a,
                                         uint32_t b0, uint32_t b1) {
    asm volatile(
        "mma.sync.aligned.m16n8k16.row.col.f32.f16.f16.f32 "
        "{%0,%1,%2,%3}, {%4,%5,%6,%7}, {%8,%9}, {%0,%1,%2,%3};"
        : "+f"(c[0]), "+f"(c[1]), "+f"(c[2]), "+f"(c[3])
        : "r"(a[0]), "r"(a[1]), "r"(a[2]), "r"(a[3]), "r"(b0), "r"(b1));
}

// ---------------------------- split kernels --------------------------------

__global__ void split_kernel(const float* __restrict__ src,
                             __half* __restrict__ dst, size_t n4,
                             int zero_counts) {
    if (zero_counts && blockIdx.x == 0 && threadIdx.x < NEXP)
        d_counts[threadIdx.x] = 0;
    size_t i = (size_t)blockIdx.x * blockDim.x + threadIdx.x;
    if (i >= n4) return;
    float4 v = ((const float4*)src)[i];
    ushort4 hv = make_ushort4(__half_as_ushort(__float2half_rn(v.x)),
                              __half_as_ushort(__float2half_rn(v.y)),
                              __half_as_ushort(__float2half_rn(v.z)),
                              __half_as_ushort(__float2half_rn(v.w)));
    *(ushort4*)(dst + 4 * i) = hv;
}

// ------------------------------ gating -------------------------------------

__global__ void gate_kernel(const float* __restrict__ x,
                            const float* __restrict__ gw, int T) {
    int warp = (blockIdx.x * blockDim.x + threadIdx.x) >> 5;
    int lane = threadIdx.x & 31;
    if (warp >= T) return;
    const float* xr = x + (size_t)warp * HID;

    double acc[NEXP];
#pragma unroll
    for (int e = 0; e < NEXP; e++) acc[e] = 0.0;
#pragma unroll 4
    for (int i = lane; i < HID; i += 32) {
        float xv = xr[i];
#pragma unroll
        for (int e = 0; e < NEXP; e++)
            acc[e] += (double)xv * (double)gw[e * HID + i];
    }
#pragma unroll
    for (int e = 0; e < NEXP; e++) {
#pragma unroll
        for (int o = 16; o > 0; o >>= 1)
            acc[e] += __shfl_down_sync(0xffffffffu, acc[e], o);
    }
    if (lane == 0) {
        float v[NEXP];
#pragma unroll
        for (int e = 0; e < NEXP; e++) v[e] = (float)acc[e];
        float bv = -1e30f, sv = -1e30f;
        int bi = 0, si = 0;
#pragma unroll
        for (int e = 0; e < NEXP; e++) {
            float val = v[e];
            if (val > bv) { sv = bv; si = bi; bv = val; bi = e; }
            else if (val > sv) { sv = val; si = e; }
        }
        float e1 = expf(sv - bv);
        float s = 1.0f + e1;
        d_slot_w[2 * warp + 0] = 1.0f / s;
        d_slot_w[2 * warp + 1] = e1 / s;
        int p0 = atomicAdd(&d_counts[bi], 1);
        d_slot_list[bi * TMAX + p0] = 2 * warp;
        int p1 = atomicAdd(&d_counts[si], 1);
        d_slot_list[si * TMAX + p1] = 2 * warp + 1;
    }
}

// ----------------------------- HMMA GEMM -----------------------------------
// CTA tile 128(M) x 128(N), BK=64 fp16 (128 B rows, xor-8 swizzle).
// 8 warps of 64x32, 2 CTAs/SM. 3 smem buffers, depth-2 cp.async in flight,
// 1 barrier per chunk.

#define BM 128
#define BN 128
#define BK 64

#define SM_BUF 1024
#define AREG   16384                  // A region: 128 rows * 128 B
#define BOFF   AREG                   // B region offset
#define BUFSZ  (AREG + 16384)         // 32768: + 128 rows * 128 B
#define NBUF   3
#define SMEM_TOTAL (SM_BUF + NBUF * BUFSZ)   // 99328 B; x2 CTAs = 194 KB/SM

template <int KDIM, int NDIM, bool FFN1>
__global__ void __launch_bounds__(256, 2)
moe_gemm_mma(const float* __restrict__ Bv)   // bias [NEXP][NDIM]
{
    constexpr int NC = KDIM / BK;     // 16 or 64

    const int e   = blockIdx.z;
    const int cnt = d_counts[e];
    const int r0  = blockIdx.y * BM;
    if (r0 >= cnt) return;
    const int n0  = blockIdx.x * BN;

    const __half* __restrict__ Wbase = FFN1 ? d_w1h : d_w2h;
    const __half* __restrict__ Abase = FFN1 ? d_xs : d_hs;

    extern __shared__ __align__(128) char smem[];
    const uint32_t sb = smem_u32(smem);
    const int tid = threadIdx.x;

    int* Srow = (int*)smem;
    if (tid < BM) {
        int idx = r0 + tid;
        Srow[tid] = (idx < cnt) ? d_slot_list[e * TMAX + idx] : -1;
    }
    __syncthreads();

    // ---- loader precompute ------------------------------------------------
    // Both A and B: row = tid>>1 (128 rows), 4 x 16B chunks at (tid&1)*4.
    const int lrow = tid >> 1;
    const int ach0 = (tid & 1) * 4;
    const uint32_t row_dst = (uint32_t)lrow * 128u;
    const int rx = lrow & 7;

    int s_ld = Srow[lrow];
    const __half* aptr;
    if (FFN1) {
        int tok = (s_ld < 0) ? 0 : (s_ld >> 1);
        aptr = Abase + (size_t)tok * KDIM;
    } else {
        aptr = Abase + (size_t)(s_ld < 0 ? 0 : s_ld) * KDIM;
    }
    const __half* bptr = Wbase + ((size_t)e * NDIM + n0 + lrow) * KDIM;

    auto load_chunk = [&](int c) {
        const uint32_t dbuf = sb + SM_BUF +
                              (uint32_t)((c % NBUF)) * BUFSZ;
        const int koff = c * BK;
#pragma unroll
        for (int i = 0; i < 4; i++) {
            int ch = ach0 + i;
            uint32_t sw = (uint32_t)((ch ^ rx) << 4);
            cp16(dbuf + row_dst + sw, aptr + koff + ch * 8);
            cp16(dbuf + BOFF + row_dst + sw, bptr + koff + ch * 8);
        }
        CP_COMMIT();
    };

    // ---- compute precompute ----------------------------------------------
    const int wid = tid >> 5, l = tid & 31;
    const int wm = wid >> 2;           // 0..1  M half (64 rows)
    const int wn = wid & 3;            // 0..3  N quarter (32 cols)
    const int g  = l >> 2, tg = l & 3;

    const int arow0 = wm * 64 + (l & 15);
    const uint32_t a_rowoff = (uint32_t)arow0 * 128u;
    const int axr = arow0 & 7;
    const int a_chsel = l >> 4;

    const int brow0 = wn * 32 + ((l >> 4) << 3) + (l & 7);
    const uint32_t b_rowoff = (uint32_t)brow0 * 128u;
    const int bxr = brow0 & 7;
    const int b_chsel = (l >> 3) & 1;

    float acc[4][4][4];
#pragma unroll
    for (int a = 0; a < 4; a++)
#pragma unroll
        for (int b = 0; b < 4; b++)
#pragma unroll
            for (int q = 0; q < 4; q++) acc[a][b][q] = 0.0f;

    // depth-2 preload (3-buffer ring)
    load_chunk(0);
    load_chunk(1);

    for (int c = 0; c < NC; c++) {
        if (c + 1 < NC) { CP_WAIT(1); }
        else            { CP_WAIT(0); }
        __syncthreads();
        // load chunk c+2 into buffer (c+2)%3 == (c-1)%3; readers of chunk
        // c-1 all passed the barrier above.
        if (c + 2 < NC) load_chunk(c + 2);

        const uint32_t sbuf = sb + SM_BUF + (uint32_t)(c % NBUF) * BUFSZ;
#pragma unroll
        for (int ks = 0; ks < BK / 16; ks++) {
            uint32_t ah[4][4];
            const uint32_t aoff =
                (uint32_t)(((2 * ks + a_chsel) ^ axr) << 4);
#pragma unroll
            for (int mi = 0; mi < 4; mi++) {
                uint32_t addr = sbuf + a_rowoff + (uint32_t)mi * 2048u + aoff;
                ldm_x4(ah[mi], addr);
            }
            const uint32_t boff =
                (uint32_t)(((2 * ks + b_chsel) ^ bxr) << 4);
#pragma unroll
            for (int jp = 0; jp < 2; jp++) {
                uint32_t baddr = sbuf + BOFF + b_rowoff +
                                 (uint32_t)jp * 2048u + boff;
                uint32_t bh[4];
                ldm_x4(bh, baddr);
#pragma unroll
                for (int mi = 0; mi < 4; mi++) {
                    mma16816(acc[mi][2 * jp],     ah[mi], bh[0], bh[1]);
                    mma16816(acc[mi][2 * jp + 1], ah[mi], bh[2], bh[3]);
                }
            }
        }
    }

    // ---- epilogue ---------------------------------------------------------
    const float* bias = Bv + (size_t)e * NDIM;
#pragma unroll
    for (int mi = 0; mi < 4; mi++) {
        const int lr0 = wm * 64 + mi * 16 + g;
        const int slotA = Srow[lr0];
        const int slotB = Srow[lr0 + 8];
#pragma unroll
        for (int nj = 0; nj < 4; nj++) {
            const int col = n0 + wn * 32 + nj * 8 + 2 * tg;
            const float b0 = bias[col], b1 = bias[col + 1];
            if (FFN1) {
                if (slotA >= 0) {
                    float v0 = acc[mi][nj][0] + b0;
                    float v1 = acc[mi][nj][1] + b1;
                    v0 = 0.5f * v0 * (1.0f + erff(v0 * 0.7071067811865475f));
                    v1 = 0.5f * v1 * (1.0f + erff(v1 * 0.7071067811865475f));
                    *(__half2*)(d_hs + (size_t)slotA * INTER + col) =
                        __floats2half2_rn(v0, v1);
                }
                if (slotB >= 0) {
                    float v0 = acc[mi][nj][2] + b0;
                    float v1 = acc[mi][nj][3] + b1;
                    v0 = 0.5f * v0 * (1.0f + erff(v0 * 0.7071067811865475f));
                    v1 = 0.5f * v1 * (1.0f + erff(v1 * 0.7071067811865475f));
                    *(__half2*)(d_hs + (size_t)slotB * INTER + col) =
                        __floats2half2_rn(v0, v1);
                }
            } else {
                if (slotA >= 0) {
                    float wmul = d_slot_w[slotA];
                    float2 o;
                    o.x = (acc[mi][nj][0] + b0) * wmul;
                    o.y = (acc[mi][nj][1] + b1) * wmul;
                    *(float2*)(d_y + (size_t)slotA * HID + col) = o;
                }
                if (slotB >= 0) {
                    float wmul = d_slot_w[slotB];
                    float2 o;
                    o.x = (acc[mi][nj][2] + b0) * wmul;
                    o.y = (acc[mi][nj][3] + b1) * wmul;
                    *(float2*)(d_y + (size_t)slotB * HID + col) = o;
                }
            }
        }
    }
}

// ------------------------------ combine ------------------------------------

__global__ void combine_kernel(float* __restrict__ out, int T) {
    int i = blockIdx.x * blockDim.x + threadIdx.x;
    int total = T * (HID / 4);
    if (i >= total) return;
    int h4 = i & (HID / 4 - 1);
    int t  = i >> 8;
    const float4* y4 = (const float4*)d_y;
    float4 a = y4[(size_t)(2 * t) * (HID / 4) + h4];
    float4 b = y4[(size_t)(2 * t + 1) * (HID / 4) + h4];
    float4 r;
    r.x = a.x + b.x; r.y = a.y + b.y; r.z = a.z + b.z; r.w = a.w + b.w;
    ((float4*)out)[i] = r;
}

// ------------------------------- launch ------------------------------------

extern "C" void kernel_launch(void* const* d_in, const int* in_sizes, int n_in,
                              void* d_out, int out_size) {
    const float* x  = (const float*)d_in[0];
    const float* gw = (const float*)d_in[1];
    const float* W1 = (const float*)d_in[2];
    const float* b1 = (const float*)d_in[3];
    const float* W2 = (const float*)d_in[4];
    const float* b2 = (const float*)d_in[5];
    float* out = (float*)d_out;

    int T = in_sizes[0] / HID;

    cudaFuncSetAttribute(moe_gemm_mma<HID, INTER, true>,
                         cudaFuncAttributeMaxDynamicSharedMemorySize,
                         SMEM_TOTAL);
    cudaFuncSetAttribute(moe_gemm_mma<INTER, HID, false>,
                         cudaFuncAttributeMaxDynamicSharedMemorySize,
                         SMEM_TOTAL);

    __half* dxs; cudaGetSymbolAddress((void**)&dxs, d_xs);
    __half* dw1; cudaGetSymbolAddress((void**)&dw1, d_w1h);
    __half* dw2; cudaGetSymbolAddress((void**)&dw2, d_w2h);

    size_t nx4 = (size_t)T * HID / 4;
    size_t nw4 = WCNT / 4;
    int mtiles = (T + BM - 1) / BM;

    // launch 0: x -> fp16 (+ zero counts)
    split_kernel<<<(unsigned)((nx4 + 255) / 256), 256>>>(x, dxs, nx4, 1);
    // launch 1: W1 -> fp16
    split_kernel<<<(unsigned)((nw4 + 255) / 256), 256>>>(W1, dw1, nw4, 0);
    // launch 2: gating
    gate_kernel<<<(T + 7) / 8, 256>>>(x, gw, T);
    // launch 3: GEMM1  (ncu target)
    dim3 g1(INTER / BN, mtiles, NEXP);
    moe_gemm_mma<HID, INTER, true><<<g1, 256, SMEM_TOTAL>>>(b1);
    // launch 4: W2 -> fp16
    split_kernel<<<(unsigned)((nw4 + 255) / 256), 256>>>(W2, dw2, nw4, 0);
    // launch 5: GEMM2
    dim3 g2(HID / BN, mtiles, NEXP);
    moe_gemm_mma<INTER, HID, false><<<g2, 256, SMEM_TOTAL>>>(b2);
    // launch 6: combine
    combine_kernel<<<(T * (HID / 4) + 255) / 256, 256>>>(out, T);
}

// round 12
// speedup vs baseline: 7.1258x; 1.0001x over previous
#include <cuda_runtime.h>
#include <cuda_bf16.h>
#include <cuda_fp16.h>
#include <math.h>
#include <stdint.h>

// ---------------------------------------------------------------------------
// MoE FFN top-2/8, H=1024, I=4096, T<=8192, fp32 in/out.
// R12: R11 (128x128 CTA, 64x32 warp tile, 2 CTAs/SM, 3-buffer cp.async ring)
// + B-fragment double-buffering across ks (hide LDSM latency intra-warp)
// + Kahan-fp32 gate (replaces fp64; -35us)
// + fused dual weight-split kernel.
// Launch order: split_x(0), split_w_dual(1), gate(2), gemm1(3 = ncu target),
//               gemm2(4), combine(5).
// ---------------------------------------------------------------------------

#define HID   1024
#define INTER 4096
#define NEXP  8
#define TMAX  8192
#define NSLOT (2 * TMAX)

#define WCNT ((size_t)NEXP * (size_t)INTER * (size_t)HID)
#define XOFF ((size_t)TMAX * (size_t)HID)
#define HOFF ((size_t)NSLOT * (size_t)INTER)

__device__ __half d_xs[XOFF];         // x fp16
__device__ __half d_w1h[WCNT];        // W1 fp16
__device__ __half d_w2h[WCNT];        // W2 fp16
__device__ __half d_hs[HOFF];         // h fp16
__device__ float  d_y[(size_t)NSLOT * (size_t)HID];
__device__ float  d_slot_w[NSLOT];
__device__ int    d_slot_list[NEXP * TMAX];
__device__ int    d_counts[NEXP];

// ------------------------------ PTX helpers --------------------------------

__device__ __forceinline__ uint32_t smem_u32(const void* p) {
    uint32_t a;
    asm("{ .reg .u64 t; cvta.to.shared.u64 t, %1; cvt.u32.u64 %0, t; }"
        : "=r"(a) : "l"(p));
    return a;
}

__device__ __forceinline__ void cp16(uint32_t saddr, const void* g) {
    asm volatile("cp.async.cg.shared.global [%0], [%1], 16;"
                 :: "r"(saddr), "l"(g));
}
#define CP_COMMIT() asm volatile("cp.async.commit_group;" ::: "memory")
#define CP_WAIT(N)  asm volatile("cp.async.wait_group %0;" :: "n"(N) : "memory")

__device__ __forceinline__ void ldm_x4(uint32_t* r, uint32_t addr) {
    asm volatile("ldmatrix.sync.aligned.m8n8.x4.shared.b16 {%0,%1,%2,%3}, [%4];"
                 : "=r"(r[0]), "=r"(r[1]), "=r"(r[2]), "=r"(r[3]) : "r"(addr));
}

__device__ __forceinline__ void mma16816(float* c, const uint32_t* a,
                                         uint32_t b0, uint32_t b1) {
    asm volatile(
        "mma.sync.aligned.m16n8k16.row.col.f32.f16.f16.f32 "
        "{%0,%1,%2,%3}, {%4,%5,%6,%7}, {%8,%9}, {%0,%1,%2,%3};"
        : "+f"(c[0]), "+f"(c[1]), "+f"(c[2]), "+f"(c[3])
        : "r"(a[0]), "r"(a[1]), "r"(a[2]), "r"(a[3]), "r"(b0), "r"(b1));
}

// ---------------------------- split kernels --------------------------------

__global__ void split_kernel(const float* __restrict__ src,
                             __half* __restrict__ dst, size_t n4,
                             int zero_counts) {
    if (zero_counts && blockIdx.x == 0 && threadIdx.x < NEXP)
        d_counts[threadIdx.x] = 0;
    size_t i = (size_t)blockIdx.x * blockDim.x + threadIdx.x;
    if (i >= n4) return;
    float4 v = ((const float4*)src)[i];
    ushort4 hv = make_ushort4(__half_as_ushort(__float2half_rn(v.x)),
                              __half_as_ushort(__float2half_rn(v.y)),
                              __half_as_ushort(__float2half_rn(v.z)),
                              __half_as_ushort(__float2half_rn(v.w)));
    *(ushort4*)(dst + 4 * i) = hv;
}

// Both weight matrices in one launch.
__global__ void split_w_dual(const float* __restrict__ s1,
                             __half* __restrict__ d1,
                             const float* __restrict__ s2,
                             __half* __restrict__ d2, size_t n4) {
    size_t i = (size_t)blockIdx.x * blockDim.x + threadIdx.x;
    const float* src;
    __half* dst;
    size_t j;
    if (i < n4)            { src = s1; dst = d1; j = i; }
    else if (i < 2 * n4)   { src = s2; dst = d2; j = i - n4; }
    else return;
    float4 v = ((const float4*)src)[j];
    ushort4 hv = make_ushort4(__half_as_ushort(__float2half_rn(v.x)),
                              __half_as_ushort(__float2half_rn(v.y)),
                              __half_as_ushort(__float2half_rn(v.z)),
                              __half_as_ushort(__float2half_rn(v.w)));
    *(ushort4*)(dst + 4 * j) = hv;
}

// ------------------------------ gating -------------------------------------
// Kahan-compensated fp32 accumulation (~1e-7 rel accuracy; routing decisions
// identical to the fp64 version in practice, at ~1/3 the cost).

__global__ void gate_kernel(const float* __restrict__ x,
                            const float* __restrict__ gw, int T) {
    int warp = (blockIdx.x * blockDim.x + threadIdx.x) >> 5;
    int lane = threadIdx.x & 31;
    if (warp >= T) return;
    const float* xr = x + (size_t)warp * HID;

    float acc[NEXP], cmp[NEXP];
#pragma unroll
    for (int e = 0; e < NEXP; e++) { acc[e] = 0.0f; cmp[e] = 0.0f; }
#pragma unroll 4
    for (int i = lane; i < HID; i += 32) {
        float xv = xr[i];
#pragma unroll
        for (int e = 0; e < NEXP; e++) {
            float prod = xv * gw[e * HID + i];
            float y = prod - cmp[e];
            float t = acc[e] + y;
            cmp[e] = (t - acc[e]) - y;
            acc[e] = t;
        }
    }
#pragma unroll
    for (int e = 0; e < NEXP; e++) {
#pragma unroll
        for (int o = 16; o > 0; o >>= 1)
            acc[e] += __shfl_down_sync(0xffffffffu, acc[e], o);
    }
    if (lane == 0) {
        float bv = -1e30f, sv = -1e30f;
        int bi = 0, si = 0;
#pragma unroll
        for (int e = 0; e < NEXP; e++) {
            float val = acc[e];
            if (val > bv) { sv = bv; si = bi; bv = val; bi = e; }
            else if (val > sv) { sv = val; si = e; }
        }
        float e1 = expf(sv - bv);
        float s = 1.0f + e1;
        d_slot_w[2 * warp + 0] = 1.0f / s;
        d_slot_w[2 * warp + 1] = e1 / s;
        int p0 = atomicAdd(&d_counts[bi], 1);
        d_slot_list[bi * TMAX + p0] = 2 * warp;
        int p1 = atomicAdd(&d_counts[si], 1);
        d_slot_list[si * TMAX + p1] = 2 * warp + 1;
    }
}

// ----------------------------- HMMA GEMM -----------------------------------
// CTA tile 128(M) x 128(N), BK=64 fp16 (128 B rows, xor-8 swizzle).
// 8 warps of 64x32, 2 CTAs/SM. 3 smem buffers, depth-2 cp.async in flight,
// 1 barrier per chunk. B fragments double-buffered across ks.

#define BM 128
#define BN 128
#define BK 64

#define SM_BUF 1024
#define AREG   16384                  // A region: 128 rows * 128 B
#define BOFF   AREG                   // B region offset
#define BUFSZ  (AREG + 16384)         // 32768
#define NBUF   3
#define SMEM_TOTAL (SM_BUF + NBUF * BUFSZ)   // 99328 B; x2 CTAs = 194 KB/SM

template <int KDIM, int NDIM, bool FFN1>
__global__ void __launch_bounds__(256, 2)
moe_gemm_mma(const float* __restrict__ Bv)   // bias [NEXP][NDIM]
{
    constexpr int NC = KDIM / BK;     // 16 or 64

    const int e   = blockIdx.z;
    const int cnt = d_counts[e];
    const int r0  = blockIdx.y * BM;
    if (r0 >= cnt) return;
    const int n0  = blockIdx.x * BN;

    const __half* __restrict__ Wbase = FFN1 ? d_w1h : d_w2h;
    const __half* __restrict__ Abase = FFN1 ? d_xs : d_hs;

    extern __shared__ __align__(128) char smem[];
    const uint32_t sb = smem_u32(smem);
    const int tid = threadIdx.x;

    int* Srow = (int*)smem;
    if (tid < BM) {
        int idx = r0 + tid;
        Srow[tid] = (idx < cnt) ? d_slot_list[e * TMAX + idx] : -1;
    }
    __syncthreads();

    // ---- loader precompute ------------------------------------------------
    const int lrow = tid >> 1;
    const int ach0 = (tid & 1) * 4;
    const uint32_t row_dst = (uint32_t)lrow * 128u;
    const int rx = lrow & 7;

    int s_ld = Srow[lrow];
    const __half* aptr;
    if (FFN1) {
        int tok = (s_ld < 0) ? 0 : (s_ld >> 1);
        aptr = Abase + (size_t)tok * KDIM;
    } else {
        aptr = Abase + (size_t)(s_ld < 0 ? 0 : s_ld) * KDIM;
    }
    const __half* bptr = Wbase + ((size_t)e * NDIM + n0 + lrow) * KDIM;

    auto load_chunk = [&](int c) {
        const uint32_t dbuf = sb + SM_BUF +
                              (uint32_t)((c % NBUF)) * BUFSZ;
        const int koff = c * BK;
#pragma unroll
        for (int i = 0; i < 4; i++) {
            int ch = ach0 + i;
            uint32_t sw = (uint32_t)((ch ^ rx) << 4);
            cp16(dbuf + row_dst + sw, aptr + koff + ch * 8);
            cp16(dbuf + BOFF + row_dst + sw, bptr + koff + ch * 8);
        }
        CP_COMMIT();
    };

    // ---- compute precompute ----------------------------------------------
    const int wid = tid >> 5, l = tid & 31;
    const int wm = wid >> 2;           // 0..1  M half (64 rows)
    const int wn = wid & 3;            // 0..3  N quarter (32 cols)
    const int g  = l >> 2, tg = l & 3;

    const int arow0 = wm * 64 + (l & 15);
    const uint32_t a_rowoff = (uint32_t)arow0 * 128u;
    const int axr = arow0 & 7;
    const int a_chsel = l >> 4;

    const int brow0 = wn * 32 + ((l >> 4) << 3) + (l & 7);
    const uint32_t b_rowoff = BOFF + (uint32_t)brow0 * 128u;
    const int bxr = brow0 & 7;
    const int b_chsel = (l >> 3) & 1;

    float acc[4][4][4];
#pragma unroll
    for (int a = 0; a < 4; a++)
#pragma unroll
        for (int b = 0; b < 4; b++)
#pragma unroll
            for (int q = 0; q < 4; q++) acc[a][b][q] = 0.0f;

    // depth-2 preload (3-buffer ring)
    load_chunk(0);
    load_chunk(1);

    for (int c = 0; c < NC; c++) {
        if (c + 1 < NC) { CP_WAIT(1); }
        else            { CP_WAIT(0); }
        __syncthreads();
        if (c + 2 < NC) load_chunk(c + 2);

        const uint32_t sbuf = sb + SM_BUF + (uint32_t)(c % NBUF) * BUFSZ;

        // B fragments double-buffered across ks: bh[buf][jp][4]
        uint32_t bh[2][2][4];
        {
            const uint32_t boff0 =
                (uint32_t)((b_chsel ^ bxr) << 4);         // ks=0 chunk
            ldm_x4(bh[0][0], sbuf + b_rowoff + boff0);
            ldm_x4(bh[0][1], sbuf + b_rowoff + 2048u + boff0);
        }
#pragma unroll
        for (int ks = 0; ks < BK / 16; ks++) {
            const int cur = ks & 1, nxt = cur ^ 1;
            uint32_t ah[4][4];
            const uint32_t aoff =
                (uint32_t)(((2 * ks + a_chsel) ^ axr) << 4);
#pragma unroll
            for (int mi = 0; mi < 4; mi++) {
                uint32_t addr = sbuf + a_rowoff + (uint32_t)mi * 2048u + aoff;
                ldm_x4(ah[mi], addr);
            }
            if (ks < BK / 16 - 1) {
                const uint32_t boffn =
                    (uint32_t)(((2 * (ks + 1) + b_chsel) ^ bxr) << 4);
                ldm_x4(bh[nxt][0], sbuf + b_rowoff + boffn);
                ldm_x4(bh[nxt][1], sbuf + b_rowoff + 2048u + boffn);
            }
#pragma unroll
            for (int jp = 0; jp < 2; jp++) {
#pragma unroll
                for (int mi = 0; mi < 4; mi++) {
                    mma16816(acc[mi][2 * jp],     ah[mi],
                             bh[cur][jp][0], bh[cur][jp][1]);
                    mma16816(acc[mi][2 * jp + 1], ah[mi],
                             bh[cur][jp][2], bh[cur][jp][3]);
                }
            }
        }
    }

    // ---- epilogue ---------------------------------------------------------
    const float* bias = Bv + (size_t)e * NDIM;
#pragma unroll
    for (int mi = 0; mi < 4; mi++) {
        const int lr0 = wm * 64 + mi * 16 + g;
        const int slotA = Srow[lr0];
        const int slotB = Srow[lr0 + 8];
#pragma unroll
        for (int nj = 0; nj < 4; nj++) {
            const int col = n0 + wn * 32 + nj * 8 + 2 * tg;
            const float b0 = bias[col], b1 = bias[col + 1];
            if (FFN1) {
                if (slotA >= 0) {
                    float v0 = acc[mi][nj][0] + b0;
                    float v1 = acc[mi][nj][1] + b1;
                    v0 = 0.5f * v0 * (1.0f + erff(v0 * 0.7071067811865475f));
                    v1 = 0.5f * v1 * (1.0f + erff(v1 * 0.7071067811865475f));
                    *(__half2*)(d_hs + (size_t)slotA * INTER + col) =
                        __floats2half2_rn(v0, v1);
                }
                if (slotB >= 0) {
                    float v0 = acc[mi][nj][2] + b0;
                    float v1 = acc[mi][nj][3] + b1;
                    v0 = 0.5f * v0 * (1.0f + erff(v0 * 0.7071067811865475f));
                    v1 = 0.5f * v1 * (1.0f + erff(v1 * 0.7071067811865475f));
                    *(__half2*)(d_hs + (size_t)slotB * INTER + col) =
                        __floats2half2_rn(v0, v1);
                }
            } else {
                if (slotA >= 0) {
                    float wmul = d_slot_w[slotA];
                    float2 o;
                    o.x = (acc[mi][nj][0] + b0) * wmul;
                    o.y = (acc[mi][nj][1] + b1) * wmul;
                    *(float2*)(d_y + (size_t)slotA * HID + col) = o;
                }
                if (slotB >= 0) {
                    float wmul = d_slot_w[slotB];
                    float2 o;
                    o.x = (acc[mi][nj][2] + b0) * wmul;
                    o.y = (acc[mi][nj][3] + b1) * wmul;
                    *(float2*)(d_y + (size_t)slotB * HID + col) = o;
                }
            }
        }
    }
}

// ------------------------------ combine ------------------------------------

__global__ void combine_kernel(float* __restrict__ out, int T) {
    int i = blockIdx.x * blockDim.x + threadIdx.x;
    int total = T * (HID / 4);
    if (i >= total) return;
    int h4 = i & (HID / 4 - 1);
    int t  = i >> 8;
    const float4* y4 = (const float4*)d_y;
    float4 a = y4[(size_t)(2 * t) * (HID / 4) + h4];
    float4 b = y4[(size_t)(2 * t + 1) * (HID / 4) + h4];
    float4 r;
    r.x = a.x + b.x; r.y = a.y + b.y; r.z = a.z + b.z; r.w = a.w + b.w;
    ((float4*)out)[i] = r;
}

// ------------------------------- launch ------------------------------------

extern "C" void kernel_launch(void* const* d_in, const int* in_sizes, int n_in,
                              void* d_out, int out_size) {
    const float* x  = (const float*)d_in[0];
    const float* gw = (const float*)d_in[1];
    const float* W1 = (const float*)d_in[2];
    const float* b1 = (const float*)d_in[3];
    const float* W2 = (const float*)d_in[4];
    const float* b2 = (const float*)d_in[5];
    float* out = (float*)d_out;

    int T = in_sizes[0] / HID;

    cudaFuncSetAttribute(moe_gemm_mma<HID, INTER, true>,
                         cudaFuncAttributeMaxDynamicSharedMemorySize,
                         SMEM_TOTAL);
    cudaFuncSetAttribute(moe_gemm_mma<INTER, HID, false>,
                         cudaFuncAttributeMaxDynamicSharedMemorySize,
                         SMEM_TOTAL);

    __half* dxs; cudaGetSymbolAddress((void**)&dxs, d_xs);
    __half* dw1; cudaGetSymbolAddress((void**)&dw1, d_w1h);
    __half* dw2; cudaGetSymbolAddress((void**)&dw2, d_w2h);

    size_t nx4 = (size_t)T * HID / 4;
    size_t nw4 = WCNT / 4;
    int mtiles = (T + BM - 1) / BM;

    // launch 0: x -> fp16 (+ zero counts)
    split_kernel<<<(unsigned)((nx4 + 255) / 256), 256>>>(x, dxs, nx4, 1);
    // launch 1: W1 & W2 -> fp16 (fused)
    split_w_dual<<<(unsigned)((2 * nw4 + 255) / 256), 256>>>(W1, dw1, W2, dw2,
                                                             nw4);
    // launch 2: gating
    gate_kernel<<<(T + 7) / 8, 256>>>(x, gw, T);
    // launch 3: GEMM1  (ncu target)
    dim3 g1(INTER / BN, mtiles, NEXP);
    moe_gemm_mma<HID, INTER, true><<<g1, 256, SMEM_TOTAL>>>(b1);
    // launch 4: GEMM2
    dim3 g2(HID / BN, mtiles, NEXP);
    moe_gemm_mma<INTER, HID, false><<<g2, 256, SMEM_TOTAL>>>(b2);
    // launch 5: combine
    combine_kernel<<<(T * (HID / 4) + 255) / 256, 256>>>(out, T);
}